// round 12
// baseline (speedup 1.0000x reference)
#include <cuda_runtime.h>
#include <cuda_bf16.h>
#include <cstdint>

// ---------------- problem dims ----------------
#define BDIM  64
#define SDIM  2048
#define EDIM  1024
#define DDIM  1024
#define SYNCD 512
#define MDIM  32
#define NHEADS 16
#define DH    64
#define SYNH  2048
#define TRH   64

typedef unsigned int uint32;

// ---------------- scratch (static device globals; no allocation) ----------------
__device__ signed char g_kva [(size_t)BDIM * SDIM * EDIM];    // int8 quantized x+zH
__device__ float g_ascale[(size_t)BDIM * SDIM];               // per-row scale of A
__device__ signed char g_wq  [(size_t)2048 * EDIM];           // int8 quantized wkvT [n][k]
__device__ float g_wscale[2048];                              // per-n scale
__device__ float g_wTf [(size_t)2048 * EDIM];                 // transposed weights fp32 (staging)
__device__ __nv_bfloat16 g_pk  [(size_t)BDIM * SDIM * EDIM];  // phi(k)
__device__ __nv_bfloat16 g_v   [(size_t)BDIM * SDIM * EDIM];  // v
__device__ float g_bias2[2048];                               // bk | bv
__device__ float g_q    [BDIM * EDIM];
__device__ float g_pq   [BDIM * EDIM];
__device__ float g_kvstate[(size_t)BDIM * NHEADS * DH * DH];  // [b*16+h][dk][dv]
__device__ float g_ksum [BDIM * NHEADS * DH];
__device__ float g_attn [BDIM * EDIM];
__device__ float g_pre  [BDIM * 2048];                        // [attn_out | activated_zL]
__device__ float g_hidden[BDIM * SYNH];
__device__ float g_state[BDIM * DDIM];
__device__ float g_partial[(size_t)8 * 64 * 2048];            // split-K partials

// ---------------- helpers ----------------
__device__ __forceinline__ float phi_f(float x) { return x > 0.f ? x + 1.f : __expf(x); }

__device__ __forceinline__ uint32 smem_u32(const void* p) {
    return (uint32)__cvta_generic_to_shared(p);
}

__device__ __forceinline__ uint32 lds32(uint32 addr) {
    uint32 v;
    asm volatile("ld.shared.b32 %0, [%1];" : "=r"(v) : "r"(addr));
    return v;
}

#define CP_ASYNC16(dst, src) \
    asm volatile("cp.async.cg.shared.global [%0], [%1], 16;" :: "r"(dst), "l"(src) : "memory")
#define CP_COMMIT() asm volatile("cp.async.commit_group;" ::: "memory")
#define CP_WAIT(n)  asm volatile("cp.async.wait_group %0;" :: "n"(n) : "memory")

__device__ __forceinline__ void mma16816(float* d, const uint32* a, const uint32* b) {
    asm volatile(
        "mma.sync.aligned.m16n8k16.row.col.f32.bf16.bf16.f32 "
        "{%0,%1,%2,%3},{%4,%5,%6,%7},{%8,%9},{%0,%1,%2,%3};\n"
        : "+f"(d[0]), "+f"(d[1]), "+f"(d[2]), "+f"(d[3])
        : "r"(a[0]), "r"(a[1]), "r"(a[2]), "r"(a[3]), "r"(b[0]), "r"(b[1]));
}

__device__ __forceinline__ void imma16832(int* d, const uint32* a, const uint32* b) {
    asm volatile(
        "mma.sync.aligned.m16n8k32.row.col.s32.s8.s8.s32 "
        "{%0,%1,%2,%3},{%4,%5,%6,%7},{%8,%9},{%0,%1,%2,%3};\n"
        : "+r"(d[0]), "+r"(d[1]), "+r"(d[2]), "+r"(d[3])
        : "r"(a[0]), "r"(a[1]), "r"(a[2]), "r"(a[3]), "r"(b[0]), "r"(b[1]));
}

// ---------------- pack: transpose wk|wv -> g_wTf[n][k] fp32 ----------------
__global__ void __launch_bounds__(256) pack_wT_kernel(const float* __restrict__ wk,
                                                      const float* __restrict__ wv) {
    __shared__ float tile[32][33];
    int tx = threadIdx.x & 31, ty = threadIdx.x >> 5;  // 32 x 8
    int n_glob0 = blockIdx.x * 32;
    int k0 = blockIdx.y * 32;
    const float* src = (n_glob0 < 1024) ? wk : wv;
    int ncol0 = (n_glob0 < 1024) ? n_glob0 : (n_glob0 - 1024);
#pragma unroll
    for (int j = 0; j < 32; j += 8) {
        int k = k0 + ty + j;
        tile[ty + j][tx] = src[(size_t)k * 1024 + ncol0 + tx];
    }
    __syncthreads();
#pragma unroll
    for (int j = 0; j < 32; j += 8) {
        int n = n_glob0 + ty + j;
        int k = k0 + tx;
        g_wTf[(size_t)n * 1024 + k] = tile[tx][ty + j];
    }
}

__global__ void biases_kernel(const float* __restrict__ bk, const float* __restrict__ bv) {
    int i = blockIdx.x * blockDim.x + threadIdx.x;
    if (i < 2048) g_bias2[i] = (i < 1024) ? bk[i] : bv[i - 1024];
}

// ---------------- quantize A: rows of (x + zH) -> int8 + per-row scale ----------------
// 1 warp per row (1024 floats): block 256 = 8 rows
__global__ void __launch_bounds__(256) quantA_kernel(const float* __restrict__ x,
                                                     const float* __restrict__ zH) {
    int row = blockIdx.x * 8 + (threadIdx.x >> 5);
    int lane = threadIdx.x & 31;
    const float4* xr = (const float4*)(x + (size_t)row * 1024);
    const float4* zr = (const float4*)(zH + (size_t)(row >> 11) * 1024);
    float4 v[8];
    float m = 0.f;
#pragma unroll
    for (int i = 0; i < 8; i++) {
        float4 a = xr[lane + 32 * i];
        float4 z = zr[lane + 32 * i];
        v[i].x = a.x + z.x; v[i].y = a.y + z.y;
        v[i].z = a.z + z.z; v[i].w = a.w + z.w;
        m = fmaxf(m, fmaxf(fmaxf(fabsf(v[i].x), fabsf(v[i].y)),
                           fmaxf(fabsf(v[i].z), fabsf(v[i].w))));
    }
#pragma unroll
    for (int off = 16; off >= 1; off >>= 1)
        m = fmaxf(m, __shfl_xor_sync(0xFFFFFFFFu, m, off));
    float inv = (m > 0.f) ? 127.f / m : 0.f;
    if (lane == 0) g_ascale[row] = m / 127.f;
    char4* dst = (char4*)(g_kva + (size_t)row * 1024);
#pragma unroll
    for (int i = 0; i < 8; i++) {
        char4 q;
        q.x = (signed char)__float2int_rn(v[i].x * inv);
        q.y = (signed char)__float2int_rn(v[i].y * inv);
        q.z = (signed char)__float2int_rn(v[i].z * inv);
        q.w = (signed char)__float2int_rn(v[i].w * inv);
        dst[lane + 32 * i] = q;
    }
}

// ---------------- quantize W rows (g_wTf) -> g_wq + g_wscale ----------------
__global__ void __launch_bounds__(256) quantW_kernel() {
    int row = blockIdx.x * 8 + (threadIdx.x >> 5);
    int lane = threadIdx.x & 31;
    const float4* src = (const float4*)(g_wTf + (size_t)row * 1024);
    float4 v[8];
    float m = 0.f;
#pragma unroll
    for (int i = 0; i < 8; i++) {
        v[i] = src[lane + 32 * i];
        m = fmaxf(m, fmaxf(fmaxf(fabsf(v[i].x), fabsf(v[i].y)),
                           fmaxf(fabsf(v[i].z), fabsf(v[i].w))));
    }
#pragma unroll
    for (int off = 16; off >= 1; off >>= 1)
        m = fmaxf(m, __shfl_xor_sync(0xFFFFFFFFu, m, off));
    float inv = (m > 0.f) ? 127.f / m : 0.f;
    if (lane == 0) g_wscale[row] = m / 127.f;
    char4* dst = (char4*)(g_wq + (size_t)row * 1024);
#pragma unroll
    for (int i = 0; i < 8; i++) {
        char4 q;
        q.x = (signed char)__float2int_rn(v[i].x * inv);
        q.y = (signed char)__float2int_rn(v[i].y * inv);
        q.z = (signed char)__float2int_rn(v[i].z * inv);
        q.w = (signed char)__float2int_rn(v[i].w * inv);
        dst[lane + 32 * i] = q;
    }
}

// ---------------- split-K small GEMM: partial[split] = A[64][Kc-slice] @ W ----------------
__global__ void __launch_bounds__(256) gemm_splitk_kernel(
    const float* __restrict__ A, int K, int Kc,
    const float* __restrict__ W, float* __restrict__ partial, int N) {
    __shared__ float sA[64][33];
    __shared__ float sW[32][65];
    int tid = threadIdx.x;
    int g = tid >> 6, nn = tid & 63;
    int n0 = blockIdx.x * 64;
    int k0 = blockIdx.y * Kc;
    float acc[16];
#pragma unroll
    for (int i = 0; i < 16; i++) acc[i] = 0.f;

    for (int kc = k0; kc < k0 + Kc; kc += 32) {
        for (int idx = tid; idx < 2048; idx += 256) {
            int bb = idx >> 5, kk = idx & 31;
            sA[bb][kk] = A[(size_t)bb * K + kc + kk];
        }
        for (int idx = tid; idx < 2048; idx += 256) {
            int kk = idx >> 6, n_ = idx & 63;
            sW[kk][n_] = W[(size_t)(kc + kk) * N + n0 + n_];
        }
        __syncthreads();
#pragma unroll 8
        for (int kk = 0; kk < 32; kk++) {
            float w = sW[kk][nn];
#pragma unroll
            for (int bl = 0; bl < 16; bl++)
                acc[bl] += sA[g * 16 + bl][kk] * w;
        }
        __syncthreads();
    }
    float* out = partial + (size_t)blockIdx.y * 64 * N;
#pragma unroll
    for (int bl = 0; bl < 16; bl++)
        out[(size_t)(g * 16 + bl) * N + n0 + nn] = acc[bl];
}

// act: 0 none, 1 relu, 2 phi
__global__ void reduce_act_kernel(const float* __restrict__ partial, int nsplit,
                                  const float* __restrict__ bias,
                                  float* __restrict__ out, int N, int out_stride, int act) {
    int i = blockIdx.x * blockDim.x + threadIdx.x;
    if (i >= 64 * N) return;
    int b = i / N, n = i - b * N;
    float acc = bias ? bias[n] : 0.f;
    for (int s = 0; s < nsplit; s++) acc += partial[(size_t)s * 64 * N + i];
    if (act == 1) acc = fmaxf(acc, 0.f);
    else if (act == 2) acc = phi_f(acc);
    out[(size_t)b * out_stride + n] = acc;
}

// ---------------- big GEMM (pipelined IMMA s8): [phi(kv@wk+bk) | kv@wv+bv] ----------------
// CTA tile 128(M) x 256(N), k-chunks of 64 s8, 4-stage cp.async, scalar-LDS fragments.
// 16 warps (512 threads), warp tile 64x32 (warp grid 2M x 8N).
#define KV_TM 128
#define KV_TN 256
#define KV_SA_BYTES (128 * 80)                 // row stride 80B = 64 s8 + 16B pad
#define KV_SB_BYTES (256 * 80)
#define KV_STAGE_BYTES (KV_SA_BYTES + KV_SB_BYTES)   // 30720
#define KV_SMEM_BYTES (4 * KV_STAGE_BYTES)           // 122880
#define KV_NCHUNK 16

__global__ void __launch_bounds__(512, 1) gemm_kv_imma_kernel() {
    extern __shared__ char sm_raw[];
    uint32 base = smem_u32(sm_raw);
    int tid = threadIdx.x, warp = tid >> 5, lane = tid & 31;
    int gid = lane >> 2, tig = lane & 3;
    int wm = warp >> 3, wn = warp & 7;             // 2 x 8 warp grid, warp tile 64x32
    int n0 = blockIdx.x * KV_TN, m0 = blockIdx.y * KV_TM;

    const signed char* baseA = g_kva + (size_t)m0 * 1024;
    const signed char* baseB = g_wq  + (size_t)n0 * 1024;

    int acc[4][4][4];
#pragma unroll
    for (int mi = 0; mi < 4; mi++)
#pragma unroll
        for (int ni = 0; ni < 4; ni++)
#pragma unroll
            for (int q = 0; q < 4; q++) acc[mi][ni][q] = 0;

    auto load_chunk = [&](int c, int s) {
        uint32 sa = base + s * KV_STAGE_BYTES;
        uint32 sb = sa + KV_SA_BYTES;
        int kc = c * 64;
        {   // A: 128 rows x 64B = 512 x 16B
            int row = tid >> 2, seg = tid & 3;
            CP_ASYNC16(sa + row * 80 + seg * 16,
                       baseA + (size_t)row * 1024 + kc + seg * 16);
        }
#pragma unroll
        for (int t = 0; t < 2; t++) {              // B: 256 rows x 64B = 1024 x 16B
            int i = tid + t * 512;
            int row = i >> 2, seg = i & 3;
            CP_ASYNC16(sb + row * 80 + seg * 16,
                       baseB + (size_t)row * 1024 + kc + seg * 16);
        }
    };

    load_chunk(0, 0); CP_COMMIT();
    load_chunk(1, 1); CP_COMMIT();
    load_chunk(2, 2); CP_COMMIT();

    // scalar fragment base offsets (bytes)
    uint32 aoff = (uint32)((wm * 64 + gid) * 80 + tig * 4);
    uint32 boff = (uint32)((wn * 32 + gid) * 80 + tig * 4);

    for (int c = 0; c < KV_NCHUNK; c++) {
        if (c <= KV_NCHUNK - 3)      { CP_WAIT(2); }
        else if (c == KV_NCHUNK - 2) { CP_WAIT(1); }
        else                         { CP_WAIT(0); }
        __syncthreads();
        if (c + 3 < KV_NCHUNK) { load_chunk(c + 3, (c + 3) & 3); CP_COMMIT(); }

        uint32 sa = base + (c & 3) * KV_STAGE_BYTES;
        uint32 sb = sa + KV_SA_BYTES;
#pragma unroll
        for (int ks = 0; ks < 2; ks++) {
            uint32 kbyte = ks * 32;                // 32 s8 per mma
            uint32 afr[4][4], bfr[4][2];
#pragma unroll
            for (int mi = 0; mi < 4; mi++) {
                uint32 a0 = sa + aoff + mi * (16 * 80) + kbyte;
                afr[mi][0] = lds32(a0);
                afr[mi][1] = lds32(a0 + 8 * 80);
                afr[mi][2] = lds32(a0 + 16);
                afr[mi][3] = lds32(a0 + 8 * 80 + 16);
            }
#pragma unroll
            for (int ni = 0; ni < 4; ni++) {
                uint32 b0 = sb + boff + ni * (8 * 80) + kbyte;
                bfr[ni][0] = lds32(b0);
                bfr[ni][1] = lds32(b0 + 16);
            }
#pragma unroll
            for (int mi = 0; mi < 4; mi++)
#pragma unroll
                for (int ni = 0; ni < 4; ni++)
                    imma16832(acc[mi][ni], afr[mi], bfr[ni]);
        }
    }

    // epilogue: rescale (ascale[m] * wscale[n]) + bias (+phi on k-half), bf16 store
    bool isk = (n0 < 1024);
    __nv_bfloat16* dst = isk ? g_pk : g_v;
    int cbase = isk ? n0 : (n0 - 1024);
#pragma unroll
    for (int mi = 0; mi < 4; mi++) {
        int r_lo = m0 + wm * 64 + mi * 16 + gid;
        float as_lo = g_ascale[r_lo];
        float as_hi = g_ascale[r_lo + 8];
#pragma unroll
        for (int ni = 0; ni < 4; ni++) {
            int col = wn * 32 + ni * 8 + tig * 2;
            int ng = n0 + col;
            float ws0 = g_wscale[ng], ws1 = g_wscale[ng + 1];
            float b0 = g_bias2[ng], b1 = g_bias2[ng + 1];
            float v00 = (float)acc[mi][ni][0] * as_lo * ws0 + b0;
            float v01 = (float)acc[mi][ni][1] * as_lo * ws1 + b1;
            float v10 = (float)acc[mi][ni][2] * as_hi * ws0 + b0;
            float v11 = (float)acc[mi][ni][3] * as_hi * ws1 + b1;
            if (isk) { v00 = phi_f(v00); v01 = phi_f(v01); v10 = phi_f(v10); v11 = phi_f(v11); }
            __nv_bfloat162 p0, p1;
            p0.x = __float2bfloat16(v00); p0.y = __float2bfloat16(v01);
            p1.x = __float2bfloat16(v10); p1.y = __float2bfloat16(v11);
            *(__nv_bfloat162*)(dst + (size_t)r_lo * 1024 + cbase + col)       = p0;
            *(__nv_bfloat162*)(dst + (size_t)(r_lo + 8) * 1024 + cbase + col) = p1;
        }
    }
}

// ---------------- kv_state[b,h] = pk^T @ v ; ksum = colsum(pk) ----------------
__global__ void __launch_bounds__(128) kvstate_kernel() {
    __shared__ __nv_bfloat16 sPk[64][34];  // transposed: [dk][s]
    __shared__ __nv_bfloat16 sV [64][34];

    int tid = threadIdx.x;
    int bh = blockIdx.x;
    int bb = bh >> 4, h = bh & 15;
    int warp = tid >> 5, lane = tid & 31, gid = lane >> 2, tig = lane & 3;

    float acc[8][4];
#pragma unroll
    for (int ni = 0; ni < 8; ni++)
#pragma unroll
        for (int q = 0; q < 4; q++) acc[ni][q] = 0.f;
    float ksum = 0.f;

    size_t base = ((size_t)bb * 2048) * 1024 + h * 64;
    for (int sc = 0; sc < 2048; sc += 32) {
#pragma unroll
        for (int t = 0; t < 8; t++) {
            int i = tid + t * 128;          // 0..1023: pair loads
            int ss = i >> 5, j = i & 31;    // dk pair j -> dk = 2j
            size_t gi = base + (size_t)(sc + ss) * 1024 + 2 * j;
            __nv_bfloat162 pk2 = *(const __nv_bfloat162*)(g_pk + gi);
            __nv_bfloat162 v2  = *(const __nv_bfloat162*)(g_v + gi);
            sPk[2 * j][ss] = pk2.x; sPk[2 * j + 1][ss] = pk2.y;
            sV [2 * j][ss] = v2.x;  sV [2 * j + 1][ss] = v2.y;
        }
        __syncthreads();
        if (tid < 64) {
#pragma unroll
            for (int ss = 0; ss < 32; ss++) ksum += __bfloat162float(sPk[tid][ss]);
        }
#pragma unroll
        for (int ks = 0; ks < 32; ks += 16) {
            uint32 afr[4], bfr[8][2];
            int rr = warp * 16;
            afr[0] = *(uint32*)&sPk[rr + gid][ks + tig * 2];
            afr[1] = *(uint32*)&sPk[rr + gid + 8][ks + tig * 2];
            afr[2] = *(uint32*)&sPk[rr + gid][ks + tig * 2 + 8];
            afr[3] = *(uint32*)&sPk[rr + gid + 8][ks + tig * 2 + 8];
#pragma unroll
            for (int ni = 0; ni < 8; ni++) {
                bfr[ni][0] = *(uint32*)&sV[ni * 8 + gid][ks + tig * 2];
                bfr[ni][1] = *(uint32*)&sV[ni * 8 + gid][ks + tig * 2 + 8];
            }
#pragma unroll
            for (int ni = 0; ni < 8; ni++) mma16816(acc[ni], afr, bfr[ni]);
        }
        __syncthreads();
    }

    float* out = g_kvstate + (size_t)bh * 4096;
#pragma unroll
    for (int ni = 0; ni < 8; ni++) {
        int col = ni * 8 + tig * 2;
        int row = warp * 16 + gid;
        out[row * 64 + col]           = acc[ni][0];
        out[row * 64 + col + 1]       = acc[ni][1];
        out[(row + 8) * 64 + col]     = acc[ni][2];
        out[(row + 8) * 64 + col + 1] = acc[ni][3];
    }
    if (tid < 64) g_ksum[(size_t)bh * 64 + tid] = ksum;
}

// ---------------- attention readout (num/den) -> g_attn; copy zL into g_pre ----------------
__global__ void __launch_bounds__(256) attn_compute_kernel(const float* __restrict__ zL) {
    __shared__ float s_pq[1024];
    __shared__ float s_den[16];
    int bb = blockIdx.x, tid = threadIdx.x;

    for (int i = tid; i < 1024; i += 256) s_pq[i] = g_pq[bb * 1024 + i];
    __syncthreads();
    if (tid < 16) {
        const float* ks = g_ksum + ((size_t)bb * 16 + tid) * 64;
        float d = 0.f;
#pragma unroll 8
        for (int k = 0; k < 64; k++) d += s_pq[tid * 64 + k] * ks[k];
        s_den[tid] = d + 1e-6f;
    }
    __syncthreads();
#pragma unroll
    for (int j = 0; j < 4; j++) {
        int e = tid + j * 256;
        int h = e >> 6, dv = e & 63;
        const float* kvs = g_kvstate + (((size_t)bb * 16 + h) * 64) * 64 + dv;
        float num = 0.f;
#pragma unroll 8
        for (int dk = 0; dk < 64; dk++) num += s_pq[h * 64 + dk] * kvs[dk * 64];
        g_attn[(size_t)bb * 1024 + e] = num / s_den[h];
        g_pre[(size_t)bb * 2048 + 1024 + e] = zL[(size_t)bb * 1024 + e];
    }
}

// ---------------- trace shift + trace processor -> both outputs ----------------
__global__ void __launch_bounds__(256) trace_kernel(const float* __restrict__ zt,
                                                    const float* __restrict__ w1,
                                                    const float* __restrict__ b1,
                                                    const float* __restrict__ w2,
                                                    const float* __restrict__ b2p,
                                                    float* __restrict__ out) {
    __shared__ float sT[64][33];
    __shared__ float sW1[32][64];
    __shared__ float sB1[64];
    __shared__ float sW2[64];
    __shared__ float sRed[4][64];
    int tid = threadIdx.x;
    int r0 = blockIdx.x * 64;
    float* out_act = out;
    float* out_tr = out + BDIM * DDIM;

    for (int idx = tid; idx < 2048; idx += 256) {
        int rr = idx >> 5, mm = idx & 31;
        float v = (mm < 31) ? zt[(size_t)(r0 + rr) * 32 + mm + 1] : g_state[r0 + rr];
        sT[rr][mm] = v;
        out_tr[(size_t)(r0 + rr) * 32 + mm] = v;
    }
    for (int idx = tid; idx < 2048; idx += 256) {
        int m = idx >> 6, hh = idx & 63;
        sW1[m][hh] = w1[idx];
    }
    if (tid < 64) { sB1[tid] = b1[tid]; sW2[tid] = w2[tid]; }
    __syncthreads();

    int rr = tid & 63, part = tid >> 6;
    float acc = 0.f;
#pragma unroll
    for (int hi = 0; hi < 16; hi++) {
        int hh = part * 16 + hi;
        float hs = sB1[hh];
#pragma unroll
        for (int m = 0; m < 32; m++) hs += sT[rr][m] * sW1[m][hh];
        acc += fmaxf(hs, 0.f) * sW2[hh];
    }
    sRed[part][rr] = acc;
    __syncthreads();
    if (tid < 64)
        out_act[r0 + tid] = sRed[0][tid] + sRed[1][tid] + sRed[2][tid] + sRed[3][tid] + b2p[0];
}

// ---------------- launch ----------------
extern "C" void kernel_launch(void* const* d_in, const int* in_sizes, int n_in,
                              void* d_out, int out_size) {
    (void)in_sizes; (void)n_in; (void)out_size;
    const float* zL  = (const float*)d_in[0];
    const float* zt  = (const float*)d_in[1];
    const float* zH  = (const float*)d_in[2];
    const float* x   = (const float*)d_in[3];
    const float* sy  = (const float*)d_in[4];
    const float* qpw = (const float*)d_in[5];
    const float* qpb = (const float*)d_in[6];
    const float* wq  = (const float*)d_in[7];
    const float* bq  = (const float*)d_in[8];
    const float* wk  = (const float*)d_in[9];
    const float* bk  = (const float*)d_in[10];
    const float* wv  = (const float*)d_in[11];
    const float* bv  = (const float*)d_in[12];
    const float* wo  = (const float*)d_in[13];
    const float* bo  = (const float*)d_in[14];
    const float* sw1 = (const float*)d_in[15];
    const float* sb1 = (const float*)d_in[16];
    const float* sw2 = (const float*)d_in[17];
    const float* sb2 = (const float*)d_in[18];
    const float* tw1 = (const float*)d_in[19];
    const float* tb1 = (const float*)d_in[20];
    const float* tw2 = (const float*)d_in[21];
    const float* tb2 = (const float*)d_in[22];
    float* out = (float*)d_out;

    float *p_q, *p_pq, *p_pre, *p_hidden, *p_state, *p_attn, *p_partial;
    cudaGetSymbolAddress((void**)&p_q,       g_q);
    cudaGetSymbolAddress((void**)&p_pq,      g_pq);
    cudaGetSymbolAddress((void**)&p_pre,     g_pre);
    cudaGetSymbolAddress((void**)&p_hidden,  g_hidden);
    cudaGetSymbolAddress((void**)&p_state,   g_state);
    cudaGetSymbolAddress((void**)&p_attn,    g_attn);
    cudaGetSymbolAddress((void**)&p_partial, g_partial);

    cudaFuncSetAttribute(gemm_kv_imma_kernel,
                         cudaFuncAttributeMaxDynamicSharedMemorySize, KV_SMEM_BYTES);

    // weight prep: transpose -> fp32 staging -> int8 + scales
    pack_wT_kernel<<<dim3(64, 32), 256>>>(wk, wv);
    quantW_kernel<<<256, 256>>>();
    biases_kernel<<<8, 256>>>(bk, bv);

    // A prep: quantize x + zH (fused) -> int8 + per-row scales
    quantA_kernel<<<16384, 256>>>(x, zH);

    // q path (split-K): q = sy@qp_w + qp_b ; pq = phi(q@wq + bq)
    gemm_splitk_kernel<<<dim3(16, 4), 256>>>(sy, SYNCD, 128, qpw, p_partial, 1024);
    reduce_act_kernel<<<256, 256>>>(p_partial, 4, qpb, p_q, 1024, 1024, 0);
    gemm_splitk_kernel<<<dim3(16, 8), 256>>>(p_q, 1024, 128, wq, p_partial, 1024);
    reduce_act_kernel<<<256, 256>>>(p_partial, 8, bq, p_pq, 1024, 1024, 2);

    // big K/V projection GEMM (pipelined int8 IMMA)
    gemm_kv_imma_kernel<<<dim3(8, 1024), 512, KV_SMEM_BYTES>>>();

    // linear-attention state
    kvstate_kernel<<<1024, 128>>>();

    // attention readout -> g_attn, copy zL -> pre[:,1024:]
    attn_compute_kernel<<<64, 256>>>(zL);

    // attn_out = g_attn @ wo + bo -> pre[:,0:1024]
    gemm_splitk_kernel<<<dim3(16, 8), 256>>>(p_attn, 1024, 128, wo, p_partial, 1024);
    reduce_act_kernel<<<256, 256>>>(p_partial, 8, bo, p_pre, 1024, 2048, 0);

    // synapse MLP
    gemm_splitk_kernel<<<dim3(32, 8), 256>>>(p_pre, 2048, 256, sw1, p_partial, 2048);
    reduce_act_kernel<<<512, 256>>>(p_partial, 8, sb1, p_hidden, 2048, 2048, 1);
    gemm_splitk_kernel<<<dim3(16, 8), 256>>>(p_hidden, 2048, 256, sw2, p_partial, 1024);
    reduce_act_kernel<<<256, 256>>>(p_partial, 8, sb2, p_state, 1024, 1024, 0);

    // trace update + processor -> writes both outputs
    trace_kernel<<<1024, 256>>>(zt, tw1, tb1, tw2, tb2, out);
}

// round 13
// speedup vs baseline: 1.5883x; 1.5883x over previous
#include <cuda_runtime.h>
#include <cuda_bf16.h>
#include <cuda_fp16.h>
#include <cstdint>

// ---------------- problem dims ----------------
#define BDIM  64
#define SDIM  2048
#define EDIM  1024
#define DDIM  1024
#define SYNCD 512
#define MDIM  32
#define NHEADS 16
#define DH    64
#define SYNH  2048
#define TRH   64

typedef unsigned int uint32;

// ---------------- scratch (static device globals; no allocation) ----------------
__device__ __half g_kv  [(size_t)BDIM * SDIM * EDIM];         // x_context + zH, fp16
__device__ __half g_wkvT[(size_t)2048 * EDIM];                // transposed: [n][k], n<1024 wk else wv
__device__ __nv_bfloat16 g_pk  [(size_t)BDIM * SDIM * EDIM];  // phi(k)
__device__ __nv_bfloat16 g_v   [(size_t)BDIM * SDIM * EDIM];  // v
__device__ float g_bias2[2048];                               // bk | bv
__device__ float g_q    [BDIM * EDIM];
__device__ float g_pq   [BDIM * EDIM];
__device__ float g_kvstate[(size_t)BDIM * NHEADS * DH * DH];  // [b*16+h][dk][dv]
__device__ float g_ksum [BDIM * NHEADS * DH];
__device__ float g_attn [BDIM * EDIM];
__device__ float g_pre  [BDIM * 2048];                        // [attn_out | activated_zL]
__device__ float g_hidden[BDIM * SYNH];
__device__ float g_state[BDIM * DDIM];
__device__ float g_partial[(size_t)8 * 64 * 2048];            // split-K partials

// ---------------- helpers ----------------
__device__ __forceinline__ float phi_f(float x) { return x > 0.f ? x + 1.f : __expf(x); }

__device__ __forceinline__ uint32 smem_u32(const void* p) {
    return (uint32)__cvta_generic_to_shared(p);
}

#define CP_ASYNC16(dst, src) \
    asm volatile("cp.async.cg.shared.global [%0], [%1], 16;" :: "r"(dst), "l"(src) : "memory")
#define CP_COMMIT() asm volatile("cp.async.commit_group;" ::: "memory")
#define CP_WAIT(n)  asm volatile("cp.async.wait_group %0;" :: "n"(n) : "memory")

#define LDSM4(r0, r1, r2, r3, addr) \
    asm volatile("ldmatrix.sync.aligned.m8n8.x4.shared.b16 {%0,%1,%2,%3}, [%4];" \
                 : "=r"(r0), "=r"(r1), "=r"(r2), "=r"(r3) : "r"(addr))

// bf16 mma, f32 accum (kvstate)
__device__ __forceinline__ void mma16816(float* d, const uint32* a, const uint32* b) {
    asm volatile(
        "mma.sync.aligned.m16n8k16.row.col.f32.bf16.bf16.f32 "
        "{%0,%1,%2,%3},{%4,%5,%6,%7},{%8,%9},{%0,%1,%2,%3};\n"
        : "+f"(d[0]), "+f"(d[1]), "+f"(d[2]), "+f"(d[3])
        : "r"(a[0]), "r"(a[1]), "r"(a[2]), "r"(a[3]), "r"(b[0]), "r"(b[1]));
}

// f16 mma, f16 accum (big GEMM hot loop — 2x issue rate if HW supports)
__device__ __forceinline__ void mma16816h(uint32* d, const uint32* a, const uint32* b) {
    asm volatile(
        "mma.sync.aligned.m16n8k16.row.col.f16.f16.f16.f16 "
        "{%0,%1},{%2,%3,%4,%5},{%6,%7},{%0,%1};\n"
        : "+r"(d[0]), "+r"(d[1])
        : "r"(a[0]), "r"(a[1]), "r"(a[2]), "r"(a[3]), "r"(b[0]), "r"(b[1]));
}

// ---------------- pack: transpose wk|wv -> g_wkvT[n][k] fp16 ----------------
__global__ void __launch_bounds__(256) pack_wT_kernel(const float* __restrict__ wk,
                                                      const float* __restrict__ wv) {
    __shared__ float tile[32][33];
    int tx = threadIdx.x & 31, ty = threadIdx.x >> 5;  // 32 x 8
    int n_glob0 = blockIdx.x * 32;
    int k0 = blockIdx.y * 32;
    const float* src = (n_glob0 < 1024) ? wk : wv;
    int ncol0 = (n_glob0 < 1024) ? n_glob0 : (n_glob0 - 1024);
#pragma unroll
    for (int j = 0; j < 32; j += 8) {
        int k = k0 + ty + j;
        tile[ty + j][tx] = src[(size_t)k * 1024 + ncol0 + tx];
    }
    __syncthreads();
#pragma unroll
    for (int j = 0; j < 32; j += 8) {
        int n = n_glob0 + ty + j;
        int k = k0 + tx;
        g_wkvT[(size_t)n * 1024 + k] = __float2half(tile[tx][ty + j]);
    }
}

__global__ void biases_kernel(const float* __restrict__ bk, const float* __restrict__ bv) {
    int i = blockIdx.x * blockDim.x + threadIdx.x;
    if (i < 2048) g_bias2[i] = (i < 1024) ? bk[i] : bv[i - 1024];
}

// ---------------- kv = x_context + zH -> fp16 ----------------
__global__ void convert_kv_kernel(const float* __restrict__ x, const float* __restrict__ zH) {
    size_t i4 = (size_t)blockIdx.x * blockDim.x + threadIdx.x;
    size_t e0 = i4 * 4;
    int e = (int)(e0 & 1023);
    int b = (int)(e0 >> 21);
    float4 xv = ((const float4*)x)[i4];
    float4 zv = *(const float4*)&zH[b * 1024 + e];
    __half2 lo = __floats2half2_rn(xv.x + zv.x, xv.y + zv.y);
    __half2 hi = __floats2half2_rn(xv.z + zv.z, xv.w + zv.w);
    ((__half2*)g_kv)[i4 * 2]     = lo;
    ((__half2*)g_kv)[i4 * 2 + 1] = hi;
}

// ---------------- split-K small GEMM: partial[split] = A[64][Kc-slice] @ W ----------------
__global__ void __launch_bounds__(256) gemm_splitk_kernel(
    const float* __restrict__ A, int K, int Kc,
    const float* __restrict__ W, float* __restrict__ partial, int N) {
    __shared__ float sA[64][33];
    __shared__ float sW[32][65];
    int tid = threadIdx.x;
    int g = tid >> 6, nn = tid & 63;
    int n0 = blockIdx.x * 64;
    int k0 = blockIdx.y * Kc;
    float acc[16];
#pragma unroll
    for (int i = 0; i < 16; i++) acc[i] = 0.f;

    for (int kc = k0; kc < k0 + Kc; kc += 32) {
        for (int idx = tid; idx < 2048; idx += 256) {
            int bb = idx >> 5, kk = idx & 31;
            sA[bb][kk] = A[(size_t)bb * K + kc + kk];
        }
        for (int idx = tid; idx < 2048; idx += 256) {
            int kk = idx >> 6, n_ = idx & 63;
            sW[kk][n_] = W[(size_t)(kc + kk) * N + n0 + n_];
        }
        __syncthreads();
#pragma unroll 8
        for (int kk = 0; kk < 32; kk++) {
            float w = sW[kk][nn];
#pragma unroll
            for (int bl = 0; bl < 16; bl++)
                acc[bl] += sA[g * 16 + bl][kk] * w;
        }
        __syncthreads();
    }
    float* out = partial + (size_t)blockIdx.y * 64 * N;
#pragma unroll
    for (int bl = 0; bl < 16; bl++)
        out[(size_t)(g * 16 + bl) * N + n0 + nn] = acc[bl];
}

// act: 0 none, 1 relu, 2 phi
__global__ void reduce_act_kernel(const float* __restrict__ partial, int nsplit,
                                  const float* __restrict__ bias,
                                  float* __restrict__ out, int N, int out_stride, int act) {
    int i = blockIdx.x * blockDim.x + threadIdx.x;
    if (i >= 64 * N) return;
    int b = i / N, n = i - b * N;
    float acc = bias ? bias[n] : 0.f;
    for (int s = 0; s < nsplit; s++) acc += partial[(size_t)s * 64 * N + i];
    if (act == 1) acc = fmaxf(acc, 0.f);
    else if (act == 2) acc = phi_f(acc);
    out[(size_t)b * out_stride + n] = acc;
}

// ---------------- big GEMM (pipelined f16-accum HMMA): [phi(kv@wk+bk) | kv@wv+bv] ----------------
// CTA tile 128(M) x 256(N), k-chunks of 32, 4-stage cp.async, ldmatrix operands.
// 16 warps (512 threads), warp tile 64x32 (2M x 8N warp grid).
// f16 accumulation within each k32 chunk, flushed to fp32 masters per chunk.
#define KV_TM 128
#define KV_TN 256
#define KV_SA_BYTES (128 * 80)                 // row stride 80B = 32 fp16 + 16B pad
#define KV_SB_BYTES (256 * 80)
#define KV_STAGE_BYTES (KV_SA_BYTES + KV_SB_BYTES)   // 30720
#define KV_SMEM_BYTES (4 * KV_STAGE_BYTES)           // 122880

__global__ void __launch_bounds__(512, 1) gemm_kv_mma_kernel() {
    extern __shared__ char sm_raw[];
    uint32 base = smem_u32(sm_raw);
    int tid = threadIdx.x, warp = tid >> 5, lane = tid & 31;
    int gid = lane >> 2, tig = lane & 3;
    int wm = warp >> 3, wn = warp & 7;             // 2 x 8 warp grid, warp tile 64x32
    int n0 = blockIdx.x * KV_TN, m0 = blockIdx.y * KV_TM;

    const __half* baseA = g_kv   + (size_t)m0 * 1024;
    const __half* baseB = g_wkvT + (size_t)n0 * 1024;

    float acc[4][4][4];
#pragma unroll
    for (int mi = 0; mi < 4; mi++)
#pragma unroll
        for (int ni = 0; ni < 4; ni++)
#pragma unroll
            for (int q = 0; q < 4; q++) acc[mi][ni][q] = 0.f;

    auto load_chunk = [&](int c, int s) {
        uint32 sa = base + s * KV_STAGE_BYTES;
        uint32 sb = sa + KV_SA_BYTES;
        int kc = c * 32;
        {   // A: 512 x 16B
            int row = tid >> 2, seg = tid & 3;
            CP_ASYNC16(sa + row * 80 + seg * 16,
                       baseA + (size_t)row * 1024 + kc + seg * 8);
        }
#pragma unroll
        for (int t = 0; t < 2; t++) {              // B: 1024 x 16B
            int i = tid + t * 512;
            int row = i >> 2, seg = i & 3;
            CP_ASYNC16(sb + row * 80 + seg * 16,
                       baseB + (size_t)row * 1024 + kc + seg * 8);
        }
    };

    load_chunk(0, 0); CP_COMMIT();
    load_chunk(1, 1); CP_COMMIT();
    load_chunk(2, 2); CP_COMMIT();

    // ldmatrix per-lane address offsets (within a stage)
    int rowA_off = (wm * 64 + (lane & 15)) * 80 + (lane >> 4) * 16;
    int rowB_off = (wn * 32 + (lane & 7) + ((lane >> 4) << 3)) * 80 + ((lane >> 3) & 1) * 16;

    for (int c = 0; c < 32; c++) {
        if (c <= 29)      { CP_WAIT(2); }
        else if (c == 30) { CP_WAIT(1); }
        else              { CP_WAIT(0); }
        __syncthreads();
        if (c + 3 < 32) { load_chunk(c + 3, (c + 3) & 3); CP_COMMIT(); }

        uint32 sa = base + (c & 3) * KV_STAGE_BYTES;
        uint32 sb = sa + KV_SA_BYTES;

        uint32 hc[4][4][2];
#pragma unroll
        for (int mi = 0; mi < 4; mi++)
#pragma unroll
            for (int ni = 0; ni < 4; ni++) { hc[mi][ni][0] = 0u; hc[mi][ni][1] = 0u; }

#pragma unroll
        for (int ks = 0; ks < 2; ks++) {
            uint32 afr[4][4], bfr[4][2];
#pragma unroll
            for (int mi = 0; mi < 4; mi++)
                LDSM4(afr[mi][0], afr[mi][1], afr[mi][2], afr[mi][3],
                      sa + rowA_off + mi * 16 * 80 + ks * 32);
#pragma unroll
            for (int nj = 0; nj < 2; nj++)
                LDSM4(bfr[2 * nj][0], bfr[2 * nj][1], bfr[2 * nj + 1][0], bfr[2 * nj + 1][1],
                      sb + rowB_off + nj * 16 * 80 + ks * 32);
#pragma unroll
            for (int mi = 0; mi < 4; mi++)
#pragma unroll
                for (int ni = 0; ni < 4; ni++)
                    mma16816h(hc[mi][ni], afr[mi], bfr[ni]);
        }

        // flush f16 chunk accumulators into fp32 masters
#pragma unroll
        for (int mi = 0; mi < 4; mi++)
#pragma unroll
            for (int ni = 0; ni < 4; ni++) {
                float2 f0 = __half22float2(*(__half2*)&hc[mi][ni][0]);
                float2 f1 = __half22float2(*(__half2*)&hc[mi][ni][1]);
                acc[mi][ni][0] += f0.x; acc[mi][ni][1] += f0.y;
                acc[mi][ni][2] += f1.x; acc[mi][ni][3] += f1.y;
            }
    }

    // epilogue: bias (+phi on k-half), bf16 store
    bool isk = (n0 < 1024);
    __nv_bfloat16* dst = isk ? g_pk : g_v;
    int cbase = isk ? n0 : (n0 - 1024);
#pragma unroll
    for (int mi = 0; mi < 4; mi++) {
        int r_lo = m0 + wm * 64 + mi * 16 + gid;
#pragma unroll
        for (int ni = 0; ni < 4; ni++) {
            int col = wn * 32 + ni * 8 + tig * 2;
            int ng = n0 + col;
            float b0 = g_bias2[ng], b1 = g_bias2[ng + 1];
            float v00 = acc[mi][ni][0] + b0, v01 = acc[mi][ni][1] + b1;
            float v10 = acc[mi][ni][2] + b0, v11 = acc[mi][ni][3] + b1;
            if (isk) { v00 = phi_f(v00); v01 = phi_f(v01); v10 = phi_f(v10); v11 = phi_f(v11); }
            __nv_bfloat162 p0, p1;
            p0.x = __float2bfloat16(v00); p0.y = __float2bfloat16(v01);
            p1.x = __float2bfloat16(v10); p1.y = __float2bfloat16(v11);
            *(__nv_bfloat162*)(dst + (size_t)r_lo * 1024 + cbase + col)       = p0;
            *(__nv_bfloat162*)(dst + (size_t)(r_lo + 8) * 1024 + cbase + col) = p1;
        }
    }
}

// ---------------- kv_state[b,h] = pk^T @ v ; ksum = colsum(pk) ----------------
__global__ void __launch_bounds__(128) kvstate_kernel() {
    __shared__ __nv_bfloat16 sPk[64][34];  // transposed: [dk][s]
    __shared__ __nv_bfloat16 sV [64][34];

    int tid = threadIdx.x;
    int bh = blockIdx.x;
    int bb = bh >> 4, h = bh & 15;
    int warp = tid >> 5, lane = tid & 31, gid = lane >> 2, tig = lane & 3;

    float acc[8][4];
#pragma unroll
    for (int ni = 0; ni < 8; ni++)
#pragma unroll
        for (int q = 0; q < 4; q++) acc[ni][q] = 0.f;
    float ksum = 0.f;

    size_t base = ((size_t)bb * 2048) * 1024 + h * 64;
    for (int sc = 0; sc < 2048; sc += 32) {
#pragma unroll
        for (int t = 0; t < 8; t++) {
            int i = tid + t * 128;          // 0..1023: pair loads
            int ss = i >> 5, j = i & 31;    // dk pair j -> dk = 2j
            size_t gi = base + (size_t)(sc + ss) * 1024 + 2 * j;
            __nv_bfloat162 pk2 = *(const __nv_bfloat162*)(g_pk + gi);
            __nv_bfloat162 v2  = *(const __nv_bfloat162*)(g_v + gi);
            sPk[2 * j][ss] = pk2.x; sPk[2 * j + 1][ss] = pk2.y;
            sV [2 * j][ss] = v2.x;  sV [2 * j + 1][ss] = v2.y;
        }
        __syncthreads();
        if (tid < 64) {
#pragma unroll
            for (int ss = 0; ss < 32; ss++) ksum += __bfloat162float(sPk[tid][ss]);
        }
#pragma unroll
        for (int ks = 0; ks < 32; ks += 16) {
            uint32 afr[4], bfr[8][2];
            int rr = warp * 16;
            afr[0] = *(uint32*)&sPk[rr + gid][ks + tig * 2];
            afr[1] = *(uint32*)&sPk[rr + gid + 8][ks + tig * 2];
            afr[2] = *(uint32*)&sPk[rr + gid][ks + tig * 2 + 8];
            afr[3] = *(uint32*)&sPk[rr + gid + 8][ks + tig * 2 + 8];
#pragma unroll
            for (int ni = 0; ni < 8; ni++) {
                bfr[ni][0] = *(uint32*)&sV[ni * 8 + gid][ks + tig * 2];
                bfr[ni][1] = *(uint32*)&sV[ni * 8 + gid][ks + tig * 2 + 8];
            }
#pragma unroll
            for (int ni = 0; ni < 8; ni++) mma16816(acc[ni], afr, bfr[ni]);
        }
        __syncthreads();
    }

    float* out = g_kvstate + (size_t)bh * 4096;
#pragma unroll
    for (int ni = 0; ni < 8; ni++) {
        int col = ni * 8 + tig * 2;
        int row = warp * 16 + gid;
        out[row * 64 + col]           = acc[ni][0];
        out[row * 64 + col + 1]       = acc[ni][1];
        out[(row + 8) * 64 + col]     = acc[ni][2];
        out[(row + 8) * 64 + col + 1] = acc[ni][3];
    }
    if (tid < 64) g_ksum[(size_t)bh * 64 + tid] = ksum;
}

// ---------------- attention readout (num/den) -> g_attn; copy zL into g_pre ----------------
__global__ void __launch_bounds__(256) attn_compute_kernel(const float* __restrict__ zL) {
    __shared__ float s_pq[1024];
    __shared__ float s_den[16];
    int bb = blockIdx.x, tid = threadIdx.x;

    for (int i = tid; i < 1024; i += 256) s_pq[i] = g_pq[bb * 1024 + i];
    __syncthreads();
    if (tid < 16) {
        const float* ks = g_ksum + ((size_t)bb * 16 + tid) * 64;
        float d = 0.f;
#pragma unroll 8
        for (int k = 0; k < 64; k++) d += s_pq[tid * 64 + k] * ks[k];
        s_den[tid] = d + 1e-6f;
    }
    __syncthreads();
#pragma unroll
    for (int j = 0; j < 4; j++) {
        int e = tid + j * 256;
        int h = e >> 6, dv = e & 63;
        const float* kvs = g_kvstate + (((size_t)bb * 16 + h) * 64) * 64 + dv;
        float num = 0.f;
#pragma unroll 8
        for (int dk = 0; dk < 64; dk++) num += s_pq[h * 64 + dk] * kvs[dk * 64];
        g_attn[(size_t)bb * 1024 + e] = num / s_den[h];
        g_pre[(size_t)bb * 2048 + 1024 + e] = zL[(size_t)bb * 1024 + e];
    }
}

// ---------------- trace shift + trace processor -> both outputs ----------------
__global__ void __launch_bounds__(256) trace_kernel(const float* __restrict__ zt,
                                                    const float* __restrict__ w1,
                                                    const float* __restrict__ b1,
                                                    const float* __restrict__ w2,
                                                    const float* __restrict__ b2p,
                                                    float* __restrict__ out) {
    __shared__ float sT[64][33];
    __shared__ float sW1[32][64];
    __shared__ float sB1[64];
    __shared__ float sW2[64];
    __shared__ float sRed[4][64];
    int tid = threadIdx.x;
    int r0 = blockIdx.x * 64;
    float* out_act = out;
    float* out_tr = out + BDIM * DDIM;

    for (int idx = tid; idx < 2048; idx += 256) {
        int rr = idx >> 5, mm = idx & 31;
        float v = (mm < 31) ? zt[(size_t)(r0 + rr) * 32 + mm + 1] : g_state[r0 + rr];
        sT[rr][mm] = v;
        out_tr[(size_t)(r0 + rr) * 32 + mm] = v;
    }
    for (int idx = tid; idx < 2048; idx += 256) {
        int m = idx >> 6, hh = idx & 63;
        sW1[m][hh] = w1[idx];
    }
    if (tid < 64) { sB1[tid] = b1[tid]; sW2[tid] = w2[tid]; }
    __syncthreads();

    int rr = tid & 63, part = tid >> 6;
    float acc = 0.f;
#pragma unroll
    for (int hi = 0; hi < 16; hi++) {
        int hh = part * 16 + hi;
        float hs = sB1[hh];
#pragma unroll
        for (int m = 0; m < 32; m++) hs += sT[rr][m] * sW1[m][hh];
        acc += fmaxf(hs, 0.f) * sW2[hh];
    }
    sRed[part][rr] = acc;
    __syncthreads();
    if (tid < 64)
        out_act[r0 + tid] = sRed[0][tid] + sRed[1][tid] + sRed[2][tid] + sRed[3][tid] + b2p[0];
}

// ---------------- launch ----------------
extern "C" void kernel_launch(void* const* d_in, const int* in_sizes, int n_in,
                              void* d_out, int out_size) {
    (void)in_sizes; (void)n_in; (void)out_size;
    const float* zL  = (const float*)d_in[0];
    const float* zt  = (const float*)d_in[1];
    const float* zH  = (const float*)d_in[2];
    const float* x   = (const float*)d_in[3];
    const float* sy  = (const float*)d_in[4];
    const float* qpw = (const float*)d_in[5];
    const float* qpb = (const float*)d_in[6];
    const float* wq  = (const float*)d_in[7];
    const float* bq  = (const float*)d_in[8];
    const float* wk  = (const float*)d_in[9];
    const float* bk  = (const float*)d_in[10];
    const float* wv  = (const float*)d_in[11];
    const float* bv  = (const float*)d_in[12];
    const float* wo  = (const float*)d_in[13];
    const float* bo  = (const float*)d_in[14];
    const float* sw1 = (const float*)d_in[15];
    const float* sb1 = (const float*)d_in[16];
    const float* sw2 = (const float*)d_in[17];
    const float* sb2 = (const float*)d_in[18];
    const float* tw1 = (const float*)d_in[19];
    const float* tb1 = (const float*)d_in[20];
    const float* tw2 = (const float*)d_in[21];
    const float* tb2 = (const float*)d_in[22];
    float* out = (float*)d_out;

    float *p_q, *p_pq, *p_pre, *p_hidden, *p_state, *p_attn, *p_partial;
    cudaGetSymbolAddress((void**)&p_q,       g_q);
    cudaGetSymbolAddress((void**)&p_pq,      g_pq);
    cudaGetSymbolAddress((void**)&p_pre,     g_pre);
    cudaGetSymbolAddress((void**)&p_hidden,  g_hidden);
    cudaGetSymbolAddress((void**)&p_state,   g_state);
    cudaGetSymbolAddress((void**)&p_attn,    g_attn);
    cudaGetSymbolAddress((void**)&p_partial, g_partial);

    cudaFuncSetAttribute(gemm_kv_mma_kernel,
                         cudaFuncAttributeMaxDynamicSharedMemorySize, KV_SMEM_BYTES);

    // weight prep
    pack_wT_kernel<<<dim3(64, 32), 256>>>(wk, wv);
    biases_kernel<<<8, 256>>>(bk, bv);
    convert_kv_kernel<<<131072, 256>>>(x, zH);

    // q path (split-K): q = sy@qp_w + qp_b ; pq = phi(q@wq + bq)
    gemm_splitk_kernel<<<dim3(16, 4), 256>>>(sy, SYNCD, 128, qpw, p_partial, 1024);
    reduce_act_kernel<<<256, 256>>>(p_partial, 4, qpb, p_q, 1024, 1024, 0);
    gemm_splitk_kernel<<<dim3(16, 8), 256>>>(p_q, 1024, 128, wq, p_partial, 1024);
    reduce_act_kernel<<<256, 256>>>(p_partial, 8, bq, p_pq, 1024, 1024, 2);

    // big K/V projection GEMM (pipelined f16-accum HMMA, 16 warps)
    gemm_kv_mma_kernel<<<dim3(8, 1024), 512, KV_SMEM_BYTES>>>();

    // linear-attention state
    kvstate_kernel<<<1024, 128>>>();

    // attention readout -> g_attn, copy zL -> pre[:,1024:]
    attn_compute_kernel<<<64, 256>>>(zL);

    // attn_out = g_attn @ wo + bo -> pre[:,0:1024]
    gemm_splitk_kernel<<<dim3(16, 8), 256>>>(p_attn, 1024, 128, wo, p_partial, 1024);
    reduce_act_kernel<<<256, 256>>>(p_partial, 8, bo, p_pre, 1024, 2048, 0);

    // synapse MLP
    gemm_splitk_kernel<<<dim3(32, 8), 256>>>(p_pre, 2048, 256, sw1, p_partial, 2048);
    reduce_act_kernel<<<512, 256>>>(p_partial, 8, sb1, p_hidden, 2048, 2048, 1);
    gemm_splitk_kernel<<<dim3(16, 8), 256>>>(p_hidden, 2048, 256, sw2, p_partial, 1024);
    reduce_act_kernel<<<256, 256>>>(p_partial, 8, sb2, p_state, 1024, 1024, 0);

    // trace update + processor -> writes both outputs
    trace_kernel<<<1024, 256>>>(zt, tw1, tb1, tw2, tb2, out);
}

// round 14
// speedup vs baseline: 2.6103x; 1.6435x over previous
#include <cuda_runtime.h>
#include <cuda_bf16.h>
#include <cstdint>

// ---------------- problem dims ----------------
#define BDIM  64
#define SDIM  2048
#define EDIM  1024
#define DDIM  1024
#define SYNCD 512
#define MDIM  32
#define NHEADS 16
#define DH    64
#define SYNH  2048
#define TRH   64

typedef unsigned int uint32;

// ---------------- scratch (static device globals; no allocation) ----------------
__device__ __nv_bfloat16 g_kv [(size_t)BDIM * SDIM * EDIM];   // x_context + zH, bf16
__device__ __nv_bfloat16 g_pk [(size_t)BDIM * SDIM * EDIM];   // phi(kv@wk+bk)
__device__ __nv_bfloat16 g_wkT[(size_t)EDIM * EDIM];          // wk transposed: [n][k]
__device__ float g_w   [(size_t)BDIM * NHEADS * SDIM];        // w[b,h,s] = pq_h . pk[b,s,h]
__device__ float g_den [BDIM * NHEADS];                       // sum_s w
__device__ float g_upart[(size_t)16 * BDIM * NHEADS * EDIM];  // split-s partials of u
__device__ float g_u   [(size_t)BDIM * NHEADS * EDIM];        // u[b,h,:] = sum_s w*kv[b,s,:]
__device__ float g_q    [BDIM * EDIM];
__device__ float g_pq   [BDIM * EDIM];
__device__ float g_attn [BDIM * EDIM];
__device__ float g_pre  [BDIM * 2048];                        // [attn_out | activated_zL]
__device__ float g_hidden[BDIM * SYNH];
__device__ float g_state[BDIM * DDIM];
__device__ float g_partial[(size_t)8 * 64 * 2048];            // split-K partials

// ---------------- helpers ----------------
__device__ __forceinline__ float phi_f(float x) { return x > 0.f ? x + 1.f : __expf(x); }

__device__ __forceinline__ uint32 smem_u32(const void* p) {
    return (uint32)__cvta_generic_to_shared(p);
}

#define CP_ASYNC16(dst, src) \
    asm volatile("cp.async.cg.shared.global [%0], [%1], 16;" :: "r"(dst), "l"(src) : "memory")
#define CP_COMMIT() asm volatile("cp.async.commit_group;" ::: "memory")
#define CP_WAIT(n)  asm volatile("cp.async.wait_group %0;" :: "n"(n) : "memory")

#define LDSM4(r0, r1, r2, r3, addr) \
    asm volatile("ldmatrix.sync.aligned.m8n8.x4.shared.b16 {%0,%1,%2,%3}, [%4];" \
                 : "=r"(r0), "=r"(r1), "=r"(r2), "=r"(r3) : "r"(addr))

__device__ __forceinline__ void mma16816(float* d, const uint32* a, const uint32* b) {
    asm volatile(
        "mma.sync.aligned.m16n8k16.row.col.f32.bf16.bf16.f32 "
        "{%0,%1,%2,%3},{%4,%5,%6,%7},{%8,%9},{%0,%1,%2,%3};\n"
        : "+f"(d[0]), "+f"(d[1]), "+f"(d[2]), "+f"(d[3])
        : "r"(a[0]), "r"(a[1]), "r"(a[2]), "r"(a[3]), "r"(b[0]), "r"(b[1]));
}

// ---------------- pack: transpose wk -> g_wkT[n][k] bf16 ----------------
__global__ void __launch_bounds__(256) pack_wT_kernel(const float* __restrict__ wk) {
    __shared__ float tile[32][33];
    int tx = threadIdx.x & 31, ty = threadIdx.x >> 5;  // 32 x 8
    int n0 = blockIdx.x * 32;
    int k0 = blockIdx.y * 32;
#pragma unroll
    for (int j = 0; j < 32; j += 8) {
        int k = k0 + ty + j;
        tile[ty + j][tx] = wk[(size_t)k * 1024 + n0 + tx];
    }
    __syncthreads();
#pragma unroll
    for (int j = 0; j < 32; j += 8) {
        int n = n0 + ty + j;
        int k = k0 + tx;
        g_wkT[(size_t)n * 1024 + k] = __float2bfloat16(tile[tx][ty + j]);
    }
}

// ---------------- kv = x_context + zH -> bf16 ----------------
__global__ void convert_kv_kernel(const float* __restrict__ x, const float* __restrict__ zH) {
    size_t i4 = (size_t)blockIdx.x * blockDim.x + threadIdx.x;
    size_t e0 = i4 * 4;
    int e = (int)(e0 & 1023);
    int b = (int)(e0 >> 21);
    float4 xv = ((const float4*)x)[i4];
    float4 zv = *(const float4*)&zH[b * 1024 + e];
    __nv_bfloat162 lo, hi;
    lo.x = __float2bfloat16(xv.x + zv.x); lo.y = __float2bfloat16(xv.y + zv.y);
    hi.x = __float2bfloat16(xv.z + zv.z); hi.y = __float2bfloat16(xv.w + zv.w);
    ((__nv_bfloat162*)g_kv)[i4 * 2]     = lo;
    ((__nv_bfloat162*)g_kv)[i4 * 2 + 1] = hi;
}

// ---------------- split-K small GEMM: partial[split] = A[64][Kc-slice] @ W ----------------
__global__ void __launch_bounds__(256) gemm_splitk_kernel(
    const float* __restrict__ A, int K, int Kc,
    const float* __restrict__ W, float* __restrict__ partial, int N) {
    __shared__ float sA[64][33];
    __shared__ float sW[32][65];
    int tid = threadIdx.x;
    int g = tid >> 6, nn = tid & 63;
    int n0 = blockIdx.x * 64;
    int k0 = blockIdx.y * Kc;
    float acc[16];
#pragma unroll
    for (int i = 0; i < 16; i++) acc[i] = 0.f;

    for (int kc = k0; kc < k0 + Kc; kc += 32) {
        for (int idx = tid; idx < 2048; idx += 256) {
            int bb = idx >> 5, kk = idx & 31;
            sA[bb][kk] = A[(size_t)bb * K + kc + kk];
        }
        for (int idx = tid; idx < 2048; idx += 256) {
            int kk = idx >> 6, n_ = idx & 63;
            sW[kk][n_] = W[(size_t)(kc + kk) * N + n0 + n_];
        }
        __syncthreads();
#pragma unroll 8
        for (int kk = 0; kk < 32; kk++) {
            float w = sW[kk][nn];
#pragma unroll
            for (int bl = 0; bl < 16; bl++)
                acc[bl] += sA[g * 16 + bl][kk] * w;
        }
        __syncthreads();
    }
    float* out = partial + (size_t)blockIdx.y * 64 * N;
#pragma unroll
    for (int bl = 0; bl < 16; bl++)
        out[(size_t)(g * 16 + bl) * N + n0 + nn] = acc[bl];
}

// act: 0 none, 1 relu, 2 phi
__global__ void reduce_act_kernel(const float* __restrict__ partial, int nsplit,
                                  const float* __restrict__ bias,
                                  float* __restrict__ out, int N, int out_stride, int act) {
    int i = blockIdx.x * blockDim.x + threadIdx.x;
    if (i >= 64 * N) return;
    int b = i / N, n = i - b * N;
    float acc = bias ? bias[n] : 0.f;
    for (int s = 0; s < nsplit; s++) acc += partial[(size_t)s * 64 * N + i];
    if (act == 1) acc = fmaxf(acc, 0.f);
    else if (act == 2) acc = phi_f(acc);
    out[(size_t)b * out_stride + n] = acc;
}

// ---------------- K projection GEMM (pipelined HMMA): pk = phi(kv@wk + bk) ----------------
// CTA tile 128(M) x 256(N), k-chunks of 32, 4-stage cp.async, ldmatrix operands.
// 16 warps (512 threads), warp tile 64x32 (2M x 8N warp grid).
#define KV_TM 128
#define KV_TN 256
#define KV_SA_BYTES (128 * 80)                 // row stride 80B = 32 bf16 + 16B pad
#define KV_SB_BYTES (256 * 80)
#define KV_STAGE_BYTES (KV_SA_BYTES + KV_SB_BYTES)   // 30720
#define KV_SMEM_BYTES (4 * KV_STAGE_BYTES)           // 122880

__global__ void __launch_bounds__(512, 1) gemm_k_mma_kernel(const float* __restrict__ bk) {
    extern __shared__ char sm_raw[];
    uint32 base = smem_u32(sm_raw);
    int tid = threadIdx.x, warp = tid >> 5, lane = tid & 31;
    int gid = lane >> 2, tig = lane & 3;
    int wm = warp >> 3, wn = warp & 7;             // 2 x 8 warp grid, warp tile 64x32
    int n0 = blockIdx.x * KV_TN, m0 = blockIdx.y * KV_TM;

    const __nv_bfloat16* baseA = g_kv  + (size_t)m0 * 1024;
    const __nv_bfloat16* baseB = g_wkT + (size_t)n0 * 1024;

    float acc[4][4][4];
#pragma unroll
    for (int mi = 0; mi < 4; mi++)
#pragma unroll
        for (int ni = 0; ni < 4; ni++)
#pragma unroll
            for (int q = 0; q < 4; q++) acc[mi][ni][q] = 0.f;

    auto load_chunk = [&](int c, int s) {
        uint32 sa = base + s * KV_STAGE_BYTES;
        uint32 sb = sa + KV_SA_BYTES;
        int kc = c * 32;
        {   // A: 512 x 16B
            int row = tid >> 2, seg = tid & 3;
            CP_ASYNC16(sa + row * 80 + seg * 16,
                       baseA + (size_t)row * 1024 + kc + seg * 8);
        }
#pragma unroll
        for (int t = 0; t < 2; t++) {              // B: 1024 x 16B
            int i = tid + t * 512;
            int row = i >> 2, seg = i & 3;
            CP_ASYNC16(sb + row * 80 + seg * 16,
                       baseB + (size_t)row * 1024 + kc + seg * 8);
        }
    };

    load_chunk(0, 0); CP_COMMIT();
    load_chunk(1, 1); CP_COMMIT();
    load_chunk(2, 2); CP_COMMIT();

    int rowA_off = (wm * 64 + (lane & 15)) * 80 + (lane >> 4) * 16;
    int rowB_off = (wn * 32 + (lane & 7) + ((lane >> 4) << 3)) * 80 + ((lane >> 3) & 1) * 16;

    for (int c = 0; c < 32; c++) {
        if (c <= 29)      { CP_WAIT(2); }
        else if (c == 30) { CP_WAIT(1); }
        else              { CP_WAIT(0); }
        __syncthreads();
        if (c + 3 < 32) { load_chunk(c + 3, (c + 3) & 3); CP_COMMIT(); }

        uint32 sa = base + (c & 3) * KV_STAGE_BYTES;
        uint32 sb = sa + KV_SA_BYTES;
#pragma unroll
        for (int ks = 0; ks < 2; ks++) {
            uint32 afr[4][4], bfr[4][2];
#pragma unroll
            for (int mi = 0; mi < 4; mi++)
                LDSM4(afr[mi][0], afr[mi][1], afr[mi][2], afr[mi][3],
                      sa + rowA_off + mi * 16 * 80 + ks * 32);
#pragma unroll
            for (int nj = 0; nj < 2; nj++)
                LDSM4(bfr[2 * nj][0], bfr[2 * nj][1], bfr[2 * nj + 1][0], bfr[2 * nj + 1][1],
                      sb + rowB_off + nj * 16 * 80 + ks * 32);
#pragma unroll
            for (int mi = 0; mi < 4; mi++)
#pragma unroll
                for (int ni = 0; ni < 4; ni++)
                    mma16816(acc[mi][ni], afr[mi], bfr[ni]);
        }
    }

    // epilogue: bias + phi, bf16 store to g_pk
#pragma unroll
    for (int mi = 0; mi < 4; mi++) {
        int r_lo = m0 + wm * 64 + mi * 16 + gid;
#pragma unroll
        for (int ni = 0; ni < 4; ni++) {
            int col = wn * 32 + ni * 8 + tig * 2;
            int ng = n0 + col;
            float b0 = bk[ng], b1 = bk[ng + 1];
            float v00 = phi_f(acc[mi][ni][0] + b0), v01 = phi_f(acc[mi][ni][1] + b1);
            float v10 = phi_f(acc[mi][ni][2] + b0), v11 = phi_f(acc[mi][ni][3] + b1);
            __nv_bfloat162 p0, p1;
            p0.x = __float2bfloat16(v00); p0.y = __float2bfloat16(v01);
            p1.x = __float2bfloat16(v10); p1.y = __float2bfloat16(v11);
            *(__nv_bfloat162*)(g_pk + (size_t)r_lo * 1024 + ng)       = p0;
            *(__nv_bfloat162*)(g_pk + (size_t)(r_lo + 8) * 1024 + ng) = p1;
        }
    }
}

// ---------------- wdot: w[b,h,s] = pq[b,h,:] . pk[b,s,h,:]; den[b,h] = sum_s w ----------------
__global__ void __launch_bounds__(256) wdot_kernel() {
    __shared__ float spq[64];
    __shared__ float sred[256];
    int bh = blockIdx.x;
    int b = bh >> 4, h = bh & 15;
    int tid = threadIdx.x;
    if (tid < 64) spq[tid] = g_pq[b * 1024 + h * 64 + tid];
    __syncthreads();

    const __nv_bfloat16* base = g_pk + ((size_t)b * 2048) * 1024 + h * 64;
    float dsum = 0.f;
#pragma unroll
    for (int i = 0; i < 8; i++) {
        int s = tid + i * 256;
        const uint4* row = (const uint4*)(base + (size_t)s * 1024);
        float acc = 0.f;
#pragma unroll
        for (int j = 0; j < 8; j++) {
            uint4 p = row[j];
            float2 f0 = __bfloat1622float2(*(__nv_bfloat162*)&p.x);
            float2 f1 = __bfloat1622float2(*(__nv_bfloat162*)&p.y);
            float2 f2 = __bfloat1622float2(*(__nv_bfloat162*)&p.z);
            float2 f3 = __bfloat1622float2(*(__nv_bfloat162*)&p.w);
            int d = j * 8;
            acc += f0.x * spq[d]     + f0.y * spq[d + 1]
                 + f1.x * spq[d + 2] + f1.y * spq[d + 3]
                 + f2.x * spq[d + 4] + f2.y * spq[d + 5]
                 + f3.x * spq[d + 6] + f3.y * spq[d + 7];
        }
        g_w[(size_t)bh * 2048 + s] = acc;
        dsum += acc;
    }
    sred[tid] = dsum;
    __syncthreads();
#pragma unroll
    for (int off = 128; off >= 1; off >>= 1) {
        if (tid < off) sred[tid] += sred[tid + off];
        __syncthreads();
    }
    if (tid == 0) g_den[bh] = sred[0];
}

// ---------------- uacc: upart[sp][b][h][:] = sum_{s in split} w[b,h,s] * kv[b,s,:] ----------------
// grid (64 b, 16 s-splits of 128), block 256 (each thread: 4 e-cols, 16 h accumulators)
__global__ void __launch_bounds__(256) uacc_kernel() {
    __shared__ float sw[16][128];
    int b = blockIdx.x, sp = blockIdx.y;
    int tid = threadIdx.x;
    for (int idx = tid; idx < 2048; idx += 256) {
        int h = idx >> 7, s = idx & 127;
        sw[h][s] = g_w[((size_t)(b * 16 + h)) * 2048 + sp * 128 + s];
    }
    __syncthreads();

    float acc[16][4];
#pragma unroll
    for (int h = 0; h < 16; h++)
#pragma unroll
        for (int q = 0; q < 4; q++) acc[h][q] = 0.f;

    const __nv_bfloat16* kvb = g_kv + ((size_t)b * 2048 + sp * 128) * 1024 + tid * 4;
    for (int s = 0; s < 128; s++) {
        uint2 kk = *(const uint2*)(kvb + (size_t)s * 1024);
        float2 e01 = __bfloat1622float2(*(__nv_bfloat162*)&kk.x);
        float2 e23 = __bfloat1622float2(*(__nv_bfloat162*)&kk.y);
#pragma unroll
        for (int h = 0; h < 16; h++) {
            float wv_ = sw[h][s];
            acc[h][0] += wv_ * e01.x; acc[h][1] += wv_ * e01.y;
            acc[h][2] += wv_ * e23.x; acc[h][3] += wv_ * e23.y;
        }
    }
    float* dst = g_upart + ((size_t)sp * 64 + b) * 16 * 1024;
#pragma unroll
    for (int h = 0; h < 16; h++) {
        float4 o; o.x = acc[h][0]; o.y = acc[h][1]; o.z = acc[h][2]; o.w = acc[h][3];
        *(float4*)(dst + h * 1024 + tid * 4) = o;
    }
}

// ---------------- ureduce: u = sum over 16 splits ----------------
__global__ void ureduce_kernel() {
    int i = blockIdx.x * 256 + threadIdx.x;
    float a = 0.f;
#pragma unroll
    for (int sp = 0; sp < 16; sp++) a += g_upart[(size_t)sp * 1048576 + i];
    g_u[i] = a;
}

// ---------------- numk: attn[b,h,e'] = (u.wv_h + den*bv) / (den + 1e-6); copy zL -> pre ----------------
// grid 1024 (b,h), block 64
__global__ void __launch_bounds__(64) numk_kernel(const float* __restrict__ wv,
                                                  const float* __restrict__ bv,
                                                  const float* __restrict__ zL) {
    __shared__ float su[1024];
    int bh = blockIdx.x;
    int b = bh >> 4, h = bh & 15;
    int tid = threadIdx.x;
    for (int i = tid; i < 1024; i += 64) su[i] = g_u[(size_t)bh * 1024 + i];
    __syncthreads();
    float den = g_den[bh];
    int col = h * 64 + tid;
    float num = den * bv[col];
    const float* wcol = wv + col;
#pragma unroll 4
    for (int e = 0; e < 1024; e++) num += su[e] * wcol[(size_t)e * 1024];
    float attn = num / (den + 1e-6f);
    g_attn[b * 1024 + col] = attn;
    g_pre[(size_t)b * 2048 + 1024 + col] = zL[b * 1024 + col];
}

// ---------------- trace shift + trace processor -> both outputs ----------------
__global__ void __launch_bounds__(256) trace_kernel(const float* __restrict__ zt,
                                                    const float* __restrict__ w1,
                                                    const float* __restrict__ b1,
                                                    const float* __restrict__ w2,
                                                    const float* __restrict__ b2p,
                                                    float* __restrict__ out) {
    __shared__ float sT[64][33];
    __shared__ float sW1[32][64];
    __shared__ float sB1[64];
    __shared__ float sW2[64];
    __shared__ float sRed[4][64];
    int tid = threadIdx.x;
    int r0 = blockIdx.x * 64;
    float* out_act = out;
    float* out_tr = out + BDIM * DDIM;

    for (int idx = tid; idx < 2048; idx += 256) {
        int rr = idx >> 5, mm = idx & 31;
        float v = (mm < 31) ? zt[(size_t)(r0 + rr) * 32 + mm + 1] : g_state[r0 + rr];
        sT[rr][mm] = v;
        out_tr[(size_t)(r0 + rr) * 32 + mm] = v;
    }
    for (int idx = tid; idx < 2048; idx += 256) {
        int m = idx >> 6, hh = idx & 63;
        sW1[m][hh] = w1[idx];
    }
    if (tid < 64) { sB1[tid] = b1[tid]; sW2[tid] = w2[tid]; }
    __syncthreads();

    int rr = tid & 63, part = tid >> 6;
    float acc = 0.f;
#pragma unroll
    for (int hi = 0; hi < 16; hi++) {
        int hh = part * 16 + hi;
        float hs = sB1[hh];
#pragma unroll
        for (int m = 0; m < 32; m++) hs += sT[rr][m] * sW1[m][hh];
        acc += fmaxf(hs, 0.f) * sW2[hh];
    }
    sRed[part][rr] = acc;
    __syncthreads();
    if (tid < 64)
        out_act[r0 + tid] = sRed[0][tid] + sRed[1][tid] + sRed[2][tid] + sRed[3][tid] + b2p[0];
}

// ---------------- launch ----------------
extern "C" void kernel_launch(void* const* d_in, const int* in_sizes, int n_in,
                              void* d_out, int out_size) {
    (void)in_sizes; (void)n_in; (void)out_size;
    const float* zL  = (const float*)d_in[0];
    const float* zt  = (const float*)d_in[1];
    const float* zH  = (const float*)d_in[2];
    const float* x   = (const float*)d_in[3];
    const float* sy  = (const float*)d_in[4];
    const float* qpw = (const float*)d_in[5];
    const float* qpb = (const float*)d_in[6];
    const float* wq  = (const float*)d_in[7];
    const float* bq  = (const float*)d_in[8];
    const float* wk  = (const float*)d_in[9];
    const float* bk  = (const float*)d_in[10];
    const float* wv  = (const float*)d_in[11];
    const float* bv  = (const float*)d_in[12];
    const float* wo  = (const float*)d_in[13];
    const float* bo  = (const float*)d_in[14];
    const float* sw1 = (const float*)d_in[15];
    const float* sb1 = (const float*)d_in[16];
    const float* sw2 = (const float*)d_in[17];
    const float* sb2 = (const float*)d_in[18];
    const float* tw1 = (const float*)d_in[19];
    const float* tb1 = (const float*)d_in[20];
    const float* tw2 = (const float*)d_in[21];
    const float* tb2 = (const float*)d_in[22];
    float* out = (float*)d_out;

    float *p_q, *p_pq, *p_pre, *p_hidden, *p_state, *p_attn, *p_partial;
    cudaGetSymbolAddress((void**)&p_q,       g_q);
    cudaGetSymbolAddress((void**)&p_pq,      g_pq);
    cudaGetSymbolAddress((void**)&p_pre,     g_pre);
    cudaGetSymbolAddress((void**)&p_hidden,  g_hidden);
    cudaGetSymbolAddress((void**)&p_state,   g_state);
    cudaGetSymbolAddress((void**)&p_attn,    g_attn);
    cudaGetSymbolAddress((void**)&p_partial, g_partial);

    cudaFuncSetAttribute(gemm_k_mma_kernel,
                         cudaFuncAttributeMaxDynamicSharedMemorySize, KV_SMEM_BYTES);

    // weight prep + activation convert
    pack_wT_kernel<<<dim3(32, 32), 256>>>(wk);
    convert_kv_kernel<<<131072, 256>>>(x, zH);

    // q path (split-K): q = sy@qp_w + qp_b ; pq = phi(q@wq + bq)
    gemm_splitk_kernel<<<dim3(16, 4), 256>>>(sy, SYNCD, 128, qpw, p_partial, 1024);
    reduce_act_kernel<<<256, 256>>>(p_partial, 4, qpb, p_q, 1024, 1024, 0);
    gemm_splitk_kernel<<<dim3(16, 8), 256>>>(p_q, 1024, 128, wq, p_partial, 1024);
    reduce_act_kernel<<<256, 256>>>(p_partial, 8, bq, p_pq, 1024, 1024, 2);

    // K projection GEMM only (V projection eliminated algebraically)
    gemm_k_mma_kernel<<<dim3(4, 1024), 512, KV_SMEM_BYTES>>>(bk);

    // linear-attention scalar weights + denominator
    wdot_kernel<<<1024, 256>>>();

    // u[b,h,:] = sum_s w * kv  (split over s, then reduce)
    uacc_kernel<<<dim3(64, 16), 256>>>();
    ureduce_kernel<<<4096, 256>>>();

    // attn = (u@wv_h + den*bv)/(den+eps); also copy zL into pre[:,1024:]
    numk_kernel<<<1024, 64>>>(wv, bv, zL);

    // attn_out = attn @ wo + bo -> pre[:,0:1024]
    gemm_splitk_kernel<<<dim3(16, 8), 256>>>(p_attn, 1024, 128, wo, p_partial, 1024);
    reduce_act_kernel<<<256, 256>>>(p_partial, 8, bo, p_pre, 1024, 2048, 0);

    // synapse MLP
    gemm_splitk_kernel<<<dim3(32, 8), 256>>>(p_pre, 2048, 256, sw1, p_partial, 2048);
    reduce_act_kernel<<<512, 256>>>(p_partial, 8, sb1, p_hidden, 2048, 2048, 1);
    gemm_splitk_kernel<<<dim3(16, 8), 256>>>(p_hidden, 2048, 256, sw2, p_partial, 1024);
    reduce_act_kernel<<<256, 256>>>(p_partial, 8, sb2, p_state, 1024, 1024, 0);

    // trace update + processor -> writes both outputs
    trace_kernel<<<1024, 256>>>(zt, tw1, tb1, tw2, tb2, out);
}

// round 15
// speedup vs baseline: 2.8010x; 1.0730x over previous
#include <cuda_runtime.h>
#include <cuda_bf16.h>
#include <cstdint>

// ---------------- problem dims ----------------
#define BDIM  64
#define SDIM  2048
#define EDIM  1024
#define DDIM  1024
#define SYNCD 512
#define MDIM  32
#define NHEADS 16
#define DH    64
#define SYNH  2048
#define TRH   64

typedef unsigned int uint32;

// ---------------- scratch (static device globals; no allocation) ----------------
__device__ __nv_bfloat16 g_kv [(size_t)BDIM * SDIM * EDIM];   // x_context + zH, bf16
__device__ __nv_bfloat16 g_wkT[(size_t)EDIM * EDIM];          // wk transposed: [n][k]
__device__ float g_wpart[2][(size_t)BDIM * NHEADS * SDIM];    // per-half-head w partials
__device__ float g_w   [(size_t)BDIM * NHEADS * SDIM];        // w[b,h,s]
__device__ float g_den [BDIM * NHEADS];                       // sum_s w
__device__ float g_upart[(size_t)16 * BDIM * NHEADS * EDIM];  // split-s partials of u
__device__ float g_q    [BDIM * EDIM];
__device__ float g_pq   [BDIM * EDIM];
__device__ float g_attn [BDIM * EDIM];
__device__ float g_pre  [BDIM * 2048];                        // [attn_out | activated_zL]
__device__ float g_hidden[BDIM * SYNH];
__device__ float g_state[BDIM * DDIM];
__device__ float g_partial[(size_t)8 * 64 * 2048];            // split-K partials

// ---------------- helpers ----------------
__device__ __forceinline__ float phi_f(float x) { return x > 0.f ? x + 1.f : __expf(x); }

__device__ __forceinline__ uint32 smem_u32(const void* p) {
    return (uint32)__cvta_generic_to_shared(p);
}

#define CP_ASYNC16(dst, src) \
    asm volatile("cp.async.cg.shared.global [%0], [%1], 16;" :: "r"(dst), "l"(src) : "memory")
#define CP_COMMIT() asm volatile("cp.async.commit_group;" ::: "memory")
#define CP_WAIT(n)  asm volatile("cp.async.wait_group %0;" :: "n"(n) : "memory")

#define LDSM4(r0, r1, r2, r3, addr) \
    asm volatile("ldmatrix.sync.aligned.m8n8.x4.shared.b16 {%0,%1,%2,%3}, [%4];" \
                 : "=r"(r0), "=r"(r1), "=r"(r2), "=r"(r3) : "r"(addr))

__device__ __forceinline__ void mma16816(float* d, const uint32* a, const uint32* b) {
    asm volatile(
        "mma.sync.aligned.m16n8k16.row.col.f32.bf16.bf16.f32 "
        "{%0,%1,%2,%3},{%4,%5,%6,%7},{%8,%9},{%0,%1,%2,%3};\n"
        : "+f"(d[0]), "+f"(d[1]), "+f"(d[2]), "+f"(d[3])
        : "r"(a[0]), "r"(a[1]), "r"(a[2]), "r"(a[3]), "r"(b[0]), "r"(b[1]));
}

// ---------------- pack: transpose wk -> g_wkT[n][k] bf16 ----------------
__global__ void __launch_bounds__(256) pack_wT_kernel(const float* __restrict__ wk) {
    __shared__ float tile[32][33];
    int tx = threadIdx.x & 31, ty = threadIdx.x >> 5;  // 32 x 8
    int n0 = blockIdx.x * 32;
    int k0 = blockIdx.y * 32;
#pragma unroll
    for (int j = 0; j < 32; j += 8) {
        int k = k0 + ty + j;
        tile[ty + j][tx] = wk[(size_t)k * 1024 + n0 + tx];
    }
    __syncthreads();
#pragma unroll
    for (int j = 0; j < 32; j += 8) {
        int n = n0 + ty + j;
        int k = k0 + tx;
        g_wkT[(size_t)n * 1024 + k] = __float2bfloat16(tile[tx][ty + j]);
    }
}

// ---------------- kv = x_context + zH -> bf16 ----------------
__global__ void convert_kv_kernel(const float* __restrict__ x, const float* __restrict__ zH) {
    size_t i4 = (size_t)blockIdx.x * blockDim.x + threadIdx.x;
    size_t e0 = i4 * 4;
    int e = (int)(e0 & 1023);
    int b = (int)(e0 >> 21);
    float4 xv = ((const float4*)x)[i4];
    float4 zv = *(const float4*)&zH[b * 1024 + e];
    __nv_bfloat162 lo, hi;
    lo.x = __float2bfloat16(xv.x + zv.x); lo.y = __float2bfloat16(xv.y + zv.y);
    hi.x = __float2bfloat16(xv.z + zv.z); hi.y = __float2bfloat16(xv.w + zv.w);
    ((__nv_bfloat162*)g_kv)[i4 * 2]     = lo;
    ((__nv_bfloat162*)g_kv)[i4 * 2 + 1] = hi;
}

// ---------------- split-K small GEMM: partial[split] = A[64][Kc-slice] @ W ----------------
__global__ void __launch_bounds__(256) gemm_splitk_kernel(
    const float* __restrict__ A, int K, int Kc,
    const float* __restrict__ W, float* __restrict__ partial, int N) {
    __shared__ float sA[64][33];
    __shared__ float sW[32][65];
    int tid = threadIdx.x;
    int g = tid >> 6, nn = tid & 63;
    int n0 = blockIdx.x * 64;
    int k0 = blockIdx.y * Kc;
    float acc[16];
#pragma unroll
    for (int i = 0; i < 16; i++) acc[i] = 0.f;

    for (int kc = k0; kc < k0 + Kc; kc += 32) {
        for (int idx = tid; idx < 2048; idx += 256) {
            int bb = idx >> 5, kk = idx & 31;
            sA[bb][kk] = A[(size_t)bb * K + kc + kk];
        }
        for (int idx = tid; idx < 2048; idx += 256) {
            int kk = idx >> 6, n_ = idx & 63;
            sW[kk][n_] = W[(size_t)(kc + kk) * N + n0 + n_];
        }
        __syncthreads();
#pragma unroll 8
        for (int kk = 0; kk < 32; kk++) {
            float w = sW[kk][nn];
#pragma unroll
            for (int bl = 0; bl < 16; bl++)
                acc[bl] += sA[g * 16 + bl][kk] * w;
        }
        __syncthreads();
    }
    float* out = partial + (size_t)blockIdx.y * 64 * N;
#pragma unroll
    for (int bl = 0; bl < 16; bl++)
        out[(size_t)(g * 16 + bl) * N + n0 + nn] = acc[bl];
}

// act: 0 none, 1 relu, 2 phi
__global__ void reduce_act_kernel(const float* __restrict__ partial, int nsplit,
                                  const float* __restrict__ bias,
                                  float* __restrict__ out, int N, int out_stride, int act) {
    int i = blockIdx.x * blockDim.x + threadIdx.x;
    if (i >= 64 * N) return;
    int b = i / N, n = i - b * N;
    float acc = bias ? bias[n] : 0.f;
    for (int s = 0; s < nsplit; s++) acc += partial[(size_t)s * 64 * N + i];
    if (act == 1) acc = fmaxf(acc, 0.f);
    else if (act == 2) acc = phi_f(acc);
    out[(size_t)b * out_stride + n] = acc;
}

// ---------------- K GEMM + fused wdot: w_part = sum over half-head of phi(kv@wk+bk)*pq --------
// CTA tile 128(M) x 256(N), k-chunks of 32, 4-stage cp.async, ldmatrix operands.
// 16 warps (512 threads), warp tile 64x32 (2M x 8N warp grid).
// Epilogue: per-row half-head dot with pq, quad-shuffle reduce, write g_wpart (no pk).
#define KV_TM 128
#define KV_TN 256
#define KV_SA_BYTES (128 * 80)                 // row stride 80B = 32 bf16 + 16B pad
#define KV_SB_BYTES (256 * 80)
#define KV_STAGE_BYTES (KV_SA_BYTES + KV_SB_BYTES)   // 30720
#define KV_SMEM_BYTES (4 * KV_STAGE_BYTES)           // 122880

__global__ void __launch_bounds__(512, 1) gemm_kw_kernel(const float* __restrict__ bk) {
    extern __shared__ char sm_raw[];
    uint32 base = smem_u32(sm_raw);
    int tid = threadIdx.x, warp = tid >> 5, lane = tid & 31;
    int gid = lane >> 2, tig = lane & 3;
    int wm = warp >> 3, wn = warp & 7;             // 2 x 8 warp grid, warp tile 64x32
    int n0 = blockIdx.x * KV_TN, m0 = blockIdx.y * KV_TM;

    const __nv_bfloat16* baseA = g_kv  + (size_t)m0 * 1024;
    const __nv_bfloat16* baseB = g_wkT + (size_t)n0 * 1024;

    float acc[4][4][4];
#pragma unroll
    for (int mi = 0; mi < 4; mi++)
#pragma unroll
        for (int ni = 0; ni < 4; ni++)
#pragma unroll
            for (int q = 0; q < 4; q++) acc[mi][ni][q] = 0.f;

    auto load_chunk = [&](int c, int s) {
        uint32 sa = base + s * KV_STAGE_BYTES;
        uint32 sb = sa + KV_SA_BYTES;
        int kc = c * 32;
        {   // A: 512 x 16B
            int row = tid >> 2, seg = tid & 3;
            CP_ASYNC16(sa + row * 80 + seg * 16,
                       baseA + (size_t)row * 1024 + kc + seg * 8);
        }
#pragma unroll
        for (int t = 0; t < 2; t++) {              // B: 1024 x 16B
            int i = tid + t * 512;
            int row = i >> 2, seg = i & 3;
            CP_ASYNC16(sb + row * 80 + seg * 16,
                       baseB + (size_t)row * 1024 + kc + seg * 8);
        }
    };

    load_chunk(0, 0); CP_COMMIT();
    load_chunk(1, 1); CP_COMMIT();
    load_chunk(2, 2); CP_COMMIT();

    int rowA_off = (wm * 64 + (lane & 15)) * 80 + (lane >> 4) * 16;
    int rowB_off = (wn * 32 + (lane & 7) + ((lane >> 4) << 3)) * 80 + ((lane >> 3) & 1) * 16;

    for (int c = 0; c < 32; c++) {
        if (c <= 29)      { CP_WAIT(2); }
        else if (c == 30) { CP_WAIT(1); }
        else              { CP_WAIT(0); }
        __syncthreads();
        if (c + 3 < 32) { load_chunk(c + 3, (c + 3) & 3); CP_COMMIT(); }

        uint32 sa = base + (c & 3) * KV_STAGE_BYTES;
        uint32 sb = sa + KV_SA_BYTES;
#pragma unroll
        for (int ks = 0; ks < 2; ks++) {
            uint32 afr[4][4], bfr[4][2];
#pragma unroll
            for (int mi = 0; mi < 4; mi++)
                LDSM4(afr[mi][0], afr[mi][1], afr[mi][2], afr[mi][3],
                      sa + rowA_off + mi * 16 * 80 + ks * 32);
#pragma unroll
            for (int nj = 0; nj < 2; nj++)
                LDSM4(bfr[2 * nj][0], bfr[2 * nj][1], bfr[2 * nj + 1][0], bfr[2 * nj + 1][1],
                      sb + rowB_off + nj * 16 * 80 + ks * 32);
#pragma unroll
            for (int mi = 0; mi < 4; mi++)
#pragma unroll
                for (int ni = 0; ni < 4; ni++)
                    mma16816(acc[mi][ni], afr[mi], bfr[ni]);
        }
    }

    // fused epilogue: w-partials = sum_{cols of this warp's half-head} phi(y+bk)*pq
    int b = m0 >> 11;                  // 2048 rows per batch, TM=128 divides evenly
    int s_base = m0 & 2047;
    int hh = (n0 >> 6) + (wn >> 1);    // global head of this warp
    int half = wn & 1;

    float pqv[8], bkv[8];
#pragma unroll
    for (int ni = 0; ni < 4; ni++) {
        int ng = n0 + wn * 32 + ni * 8 + tig * 2;
        pqv[2 * ni]     = g_pq[b * 1024 + ng];
        pqv[2 * ni + 1] = g_pq[b * 1024 + ng + 1];
        bkv[2 * ni]     = bk[ng];
        bkv[2 * ni + 1] = bk[ng + 1];
    }
    float* wp = g_wpart[half] + (size_t)(b * 16 + hh) * 2048;
#pragma unroll
    for (int mi = 0; mi < 4; mi++) {
        float p0 = 0.f, p1 = 0.f;
#pragma unroll
        for (int ni = 0; ni < 4; ni++) {
            p0 += phi_f(acc[mi][ni][0] + bkv[2 * ni]) * pqv[2 * ni]
                + phi_f(acc[mi][ni][1] + bkv[2 * ni + 1]) * pqv[2 * ni + 1];
            p1 += phi_f(acc[mi][ni][2] + bkv[2 * ni]) * pqv[2 * ni]
                + phi_f(acc[mi][ni][3] + bkv[2 * ni + 1]) * pqv[2 * ni + 1];
        }
        p0 += __shfl_xor_sync(0xFFFFFFFFu, p0, 1);
        p0 += __shfl_xor_sync(0xFFFFFFFFu, p0, 2);
        p1 += __shfl_xor_sync(0xFFFFFFFFu, p1, 1);
        p1 += __shfl_xor_sync(0xFFFFFFFFu, p1, 2);
        if (tig == 0) {
            int s0 = s_base + wm * 64 + mi * 16 + gid;
            wp[s0]     = p0;
            wp[s0 + 8] = p1;
        }
    }
}

// ---------------- wden: w = part0 + part1 ; den = sum_s w ----------------
__global__ void __launch_bounds__(256) wden_kernel() {
    __shared__ float sred[256];
    int bh = blockIdx.x, tid = threadIdx.x;
    size_t base = (size_t)bh * 2048;
    float dsum = 0.f;
#pragma unroll
    for (int i = 0; i < 8; i++) {
        int s = tid + i * 256;
        float wv = g_wpart[0][base + s] + g_wpart[1][base + s];
        g_w[base + s] = wv;
        dsum += wv;
    }
    sred[tid] = dsum;
    __syncthreads();
#pragma unroll
    for (int off = 128; off >= 1; off >>= 1) {
        if (tid < off) sred[tid] += sred[tid + off];
        __syncthreads();
    }
    if (tid == 0) g_den[bh] = sred[0];
}

// ---------------- uacc: upart[sp][b][h][:] = sum_{s in split} w[b,h,s] * kv[b,s,:] ----------------
__global__ void __launch_bounds__(256) uacc_kernel() {
    __shared__ float sw[16][128];
    int b = blockIdx.x, sp = blockIdx.y;
    int tid = threadIdx.x;
    for (int idx = tid; idx < 2048; idx += 256) {
        int h = idx >> 7, s = idx & 127;
        sw[h][s] = g_w[((size_t)(b * 16 + h)) * 2048 + sp * 128 + s];
    }
    __syncthreads();

    float acc[16][4];
#pragma unroll
    for (int h = 0; h < 16; h++)
#pragma unroll
        for (int q = 0; q < 4; q++) acc[h][q] = 0.f;

    const __nv_bfloat16* kvb = g_kv + ((size_t)b * 2048 + sp * 128) * 1024 + tid * 4;
    for (int s = 0; s < 128; s++) {
        uint2 kk = *(const uint2*)(kvb + (size_t)s * 1024);
        float2 e01 = __bfloat1622float2(*(__nv_bfloat162*)&kk.x);
        float2 e23 = __bfloat1622float2(*(__nv_bfloat162*)&kk.y);
#pragma unroll
        for (int h = 0; h < 16; h++) {
            float wv_ = sw[h][s];
            acc[h][0] += wv_ * e01.x; acc[h][1] += wv_ * e01.y;
            acc[h][2] += wv_ * e23.x; acc[h][3] += wv_ * e23.y;
        }
    }
    float* dst = g_upart + ((size_t)sp * 64 + b) * 16 * 1024;
#pragma unroll
    for (int h = 0; h < 16; h++) {
        float4 o; o.x = acc[h][0]; o.y = acc[h][1]; o.z = acc[h][2]; o.w = acc[h][3];
        *(float4*)(dst + h * 1024 + tid * 4) = o;
    }
}

// ---------------- numk: reduce upart -> u ; attn = (u.wv_h + den*bv)/(den+eps); copy zL -------
// grid 1024 (b,h), block 256: 4 e-groups of 256, smem-reduced
__global__ void __launch_bounds__(256) numk_kernel(const float* __restrict__ wv,
                                                   const float* __restrict__ bv,
                                                   const float* __restrict__ zL) {
    __shared__ float su[1024];
    __shared__ float sred[4][64];
    int bh = blockIdx.x;
    int b = bh >> 4, h = bh & 15;
    int tid = threadIdx.x;
    for (int i = tid; i < 1024; i += 256) {
        float a = 0.f;
#pragma unroll
        for (int sp = 0; sp < 16; sp++)
            a += g_upart[(((size_t)sp * 64 + b) * 16 + h) * 1024 + i];
        su[i] = a;
    }
    __syncthreads();
    int grp = tid >> 6, c = tid & 63;
    int col = h * 64 + c;
    const float* wcol = wv + col;
    float part = 0.f;
#pragma unroll 4
    for (int e = grp * 256; e < grp * 256 + 256; e++)
        part += su[e] * wcol[(size_t)e * 1024];
    sred[grp][c] = part;
    __syncthreads();
    if (tid < 64) {
        float den = g_den[bh];
        float num = sred[0][tid] + sred[1][tid] + sred[2][tid] + sred[3][tid]
                  + den * bv[h * 64 + tid];
        float attn = num / (den + 1e-6f);
        g_attn[b * 1024 + h * 64 + tid] = attn;
        g_pre[(size_t)b * 2048 + 1024 + h * 64 + tid] = zL[b * 1024 + h * 64 + tid];
    }
}

// ---------------- trace shift + trace processor -> both outputs ----------------
__global__ void __launch_bounds__(256) trace_kernel(const float* __restrict__ zt,
                                                    const float* __restrict__ w1,
                                                    const float* __restrict__ b1,
                                                    const float* __restrict__ w2,
                                                    const float* __restrict__ b2p,
                                                    float* __restrict__ out) {
    __shared__ float sT[64][33];
    __shared__ float sW1[32][64];
    __shared__ float sB1[64];
    __shared__ float sW2[64];
    __shared__ float sRed[4][64];
    int tid = threadIdx.x;
    int r0 = blockIdx.x * 64;
    float* out_act = out;
    float* out_tr = out + BDIM * DDIM;

    for (int idx = tid; idx < 2048; idx += 256) {
        int rr = idx >> 5, mm = idx & 31;
        float v = (mm < 31) ? zt[(size_t)(r0 + rr) * 32 + mm + 1] : g_state[r0 + rr];
        sT[rr][mm] = v;
        out_tr[(size_t)(r0 + rr) * 32 + mm] = v;
    }
    for (int idx = tid; idx < 2048; idx += 256) {
        int m = idx >> 6, hh = idx & 63;
        sW1[m][hh] = w1[idx];
    }
    if (tid < 64) { sB1[tid] = b1[tid]; sW2[tid] = w2[tid]; }
    __syncthreads();

    int rr = tid & 63, part = tid >> 6;
    float acc = 0.f;
#pragma unroll
    for (int hi = 0; hi < 16; hi++) {
        int hh = part * 16 + hi;
        float hs = sB1[hh];
#pragma unroll
        for (int m = 0; m < 32; m++) hs += sT[rr][m] * sW1[m][hh];
        acc += fmaxf(hs, 0.f) * sW2[hh];
    }
    sRed[part][rr] = acc;
    __syncthreads();
    if (tid < 64)
        out_act[r0 + tid] = sRed[0][tid] + sRed[1][tid] + sRed[2][tid] + sRed[3][tid] + b2p[0];
}

// ---------------- launch ----------------
extern "C" void kernel_launch(void* const* d_in, const int* in_sizes, int n_in,
                              void* d_out, int out_size) {
    (void)in_sizes; (void)n_in; (void)out_size;
    const float* zL  = (const float*)d_in[0];
    const float* zt  = (const float*)d_in[1];
    const float* zH  = (const float*)d_in[2];
    const float* x   = (const float*)d_in[3];
    const float* sy  = (const float*)d_in[4];
    const float* qpw = (const float*)d_in[5];
    const float* qpb = (const float*)d_in[6];
    const float* wq  = (const float*)d_in[7];
    const float* bq  = (const float*)d_in[8];
    const float* wk  = (const float*)d_in[9];
    const float* bk  = (const float*)d_in[10];
    const float* wv  = (const float*)d_in[11];
    const float* bv  = (const float*)d_in[12];
    const float* wo  = (const float*)d_in[13];
    const float* bo  = (const float*)d_in[14];
    const float* sw1 = (const float*)d_in[15];
    const float* sb1 = (const float*)d_in[16];
    const float* sw2 = (const float*)d_in[17];
    const float* sb2 = (const float*)d_in[18];
    const float* tw1 = (const float*)d_in[19];
    const float* tb1 = (const float*)d_in[20];
    const float* tw2 = (const float*)d_in[21];
    const float* tb2 = (const float*)d_in[22];
    float* out = (float*)d_out;

    float *p_q, *p_pq, *p_pre, *p_hidden, *p_state, *p_attn, *p_partial;
    cudaGetSymbolAddress((void**)&p_q,       g_q);
    cudaGetSymbolAddress((void**)&p_pq,      g_pq);
    cudaGetSymbolAddress((void**)&p_pre,     g_pre);
    cudaGetSymbolAddress((void**)&p_hidden,  g_hidden);
    cudaGetSymbolAddress((void**)&p_state,   g_state);
    cudaGetSymbolAddress((void**)&p_attn,    g_attn);
    cudaGetSymbolAddress((void**)&p_partial, g_partial);

    cudaFuncSetAttribute(gemm_kw_kernel,
                         cudaFuncAttributeMaxDynamicSharedMemorySize, KV_SMEM_BYTES);

    // weight prep + activation convert
    pack_wT_kernel<<<dim3(32, 32), 256>>>(wk);
    convert_kv_kernel<<<131072, 256>>>(x, zH);

    // q path (split-K): q = sy@qp_w + qp_b ; pq = phi(q@wq + bq)
    gemm_splitk_kernel<<<dim3(16, 4), 256>>>(sy, SYNCD, 128, qpw, p_partial, 1024);
    reduce_act_kernel<<<256, 256>>>(p_partial, 4, qpb, p_q, 1024, 1024, 0);
    gemm_splitk_kernel<<<dim3(16, 8), 256>>>(p_q, 1024, 128, wq, p_partial, 1024);
    reduce_act_kernel<<<256, 256>>>(p_partial, 8, bq, p_pq, 1024, 1024, 2);

    // K projection GEMM with fused wdot epilogue (pk never materialized)
    gemm_kw_kernel<<<dim3(4, 1024), 512, KV_SMEM_BYTES>>>(bk);

    // w = part0+part1 ; den = sum_s w
    wden_kernel<<<1024, 256>>>();

    // u partials over s-splits
    uacc_kernel<<<dim3(64, 16), 256>>>();

    // reduce upart + attn = (u@wv_h + den*bv)/(den+eps); copy zL -> pre[:,1024:]
    numk_kernel<<<1024, 256>>>(wv, bv, zL);

    // attn_out = attn @ wo + bo -> pre[:,0:1024]
    gemm_splitk_kernel<<<dim3(16, 8), 256>>>(p_attn, 1024, 128, wo, p_partial, 1024);
    reduce_act_kernel<<<256, 256>>>(p_partial, 8, bo, p_pre, 1024, 2048, 0);

    // synapse MLP
    gemm_splitk_kernel<<<dim3(32, 8), 256>>>(p_pre, 2048, 256, sw1, p_partial, 2048);
    reduce_act_kernel<<<512, 256>>>(p_partial, 8, sb1, p_hidden, 2048, 2048, 1);
    gemm_splitk_kernel<<<dim3(16, 8), 256>>>(p_hidden, 2048, 256, sw2, p_partial, 1024);
    reduce_act_kernel<<<256, 256>>>(p_partial, 8, sb2, p_state, 1024, 1024, 0);

    // trace update + processor -> writes both outputs
    trace_kernel<<<1024, 256>>>(zt, tw1, tb1, tw2, tb2, out);
}

// round 16
// speedup vs baseline: 3.2319x; 1.1538x over previous
#include <cuda_runtime.h>
#include <cuda_bf16.h>
#include <cstdint>

// ---------------- problem dims ----------------
#define BDIM  64
#define SDIM  2048
#define EDIM  1024
#define DDIM  1024
#define SYNCD 512
#define MDIM  32
#define NHEADS 16
#define DH    64
#define SYNH  2048
#define TRH   64

typedef unsigned int uint32;

// ---------------- scratch (static device globals; no allocation) ----------------
__device__ __nv_bfloat16 g_kv [(size_t)BDIM * SDIM * EDIM];   // x_context + zH, bf16
__device__ __nv_bfloat16 g_wkT[(size_t)EDIM * EDIM];          // wk transposed: [n][k]
__device__ float g_wpart[2][(size_t)BDIM * NHEADS * SDIM];    // per-half-head w partials
__device__ __nv_bfloat16 g_wbf[(size_t)BDIM * NHEADS * SDIM]; // w[b,h,s] bf16 (for ugemm)
__device__ float g_den [BDIM * NHEADS];                       // sum_s w (fp32 exact)
__device__ float g_u   [(size_t)BDIM * NHEADS * EDIM];        // u[b,h,:] = sum_s w*kv[b,s,:]
__device__ float g_q    [BDIM * EDIM];
__device__ float g_pq   [BDIM * EDIM];
__device__ float g_attn [BDIM * EDIM];
__device__ float g_pre  [BDIM * 2048];                        // [attn_out | activated_zL]
__device__ float g_hidden[BDIM * SYNH];
__device__ float g_state[BDIM * DDIM];
__device__ float g_partial[(size_t)8 * 64 * 2048];            // split-K partials

// ---------------- helpers ----------------
__device__ __forceinline__ float phi_f(float x) { return x > 0.f ? x + 1.f : __expf(x); }

__device__ __forceinline__ uint32 smem_u32(const void* p) {
    return (uint32)__cvta_generic_to_shared(p);
}

#define CP_ASYNC16(dst, src) \
    asm volatile("cp.async.cg.shared.global [%0], [%1], 16;" :: "r"(dst), "l"(src) : "memory")
#define CP_COMMIT() asm volatile("cp.async.commit_group;" ::: "memory")
#define CP_WAIT(n)  asm volatile("cp.async.wait_group %0;" :: "n"(n) : "memory")

#define LDSM4(r0, r1, r2, r3, addr) \
    asm volatile("ldmatrix.sync.aligned.m8n8.x4.shared.b16 {%0,%1,%2,%3}, [%4];" \
                 : "=r"(r0), "=r"(r1), "=r"(r2), "=r"(r3) : "r"(addr))

__device__ __forceinline__ void mma16816(float* d, const uint32* a, const uint32* b) {
    asm volatile(
        "mma.sync.aligned.m16n8k16.row.col.f32.bf16.bf16.f32 "
        "{%0,%1,%2,%3},{%4,%5,%6,%7},{%8,%9},{%0,%1,%2,%3};\n"
        : "+f"(d[0]), "+f"(d[1]), "+f"(d[2]), "+f"(d[3])
        : "r"(a[0]), "r"(a[1]), "r"(a[2]), "r"(a[3]), "r"(b[0]), "r"(b[1]));
}

// ---------------- pack: transpose wk -> g_wkT[n][k] bf16 ----------------
__global__ void __launch_bounds__(256) pack_wT_kernel(const float* __restrict__ wk) {
    __shared__ float tile[32][33];
    int tx = threadIdx.x & 31, ty = threadIdx.x >> 5;  // 32 x 8
    int n0 = blockIdx.x * 32;
    int k0 = blockIdx.y * 32;
#pragma unroll
    for (int j = 0; j < 32; j += 8) {
        int k = k0 + ty + j;
        tile[ty + j][tx] = wk[(size_t)k * 1024 + n0 + tx];
    }
    __syncthreads();
#pragma unroll
    for (int j = 0; j < 32; j += 8) {
        int n = n0 + ty + j;
        int k = k0 + tx;
        g_wkT[(size_t)n * 1024 + k] = __float2bfloat16(tile[tx][ty + j]);
    }
}

// ---------------- kv = x_context + zH -> bf16 ----------------
__global__ void convert_kv_kernel(const float* __restrict__ x, const float* __restrict__ zH) {
    size_t i4 = (size_t)blockIdx.x * blockDim.x + threadIdx.x;
    size_t e0 = i4 * 4;
    int e = (int)(e0 & 1023);
    int b = (int)(e0 >> 21);
    float4 xv = ((const float4*)x)[i4];
    float4 zv = *(const float4*)&zH[b * 1024 + e];
    __nv_bfloat162 lo, hi;
    lo.x = __float2bfloat16(xv.x + zv.x); lo.y = __float2bfloat16(xv.y + zv.y);
    hi.x = __float2bfloat16(xv.z + zv.z); hi.y = __float2bfloat16(xv.w + zv.w);
    ((__nv_bfloat162*)g_kv)[i4 * 2]     = lo;
    ((__nv_bfloat162*)g_kv)[i4 * 2 + 1] = hi;
}

// ---------------- split-K small GEMM: partial[split] = A[64][Kc-slice] @ W ----------------
__global__ void __launch_bounds__(256) gemm_splitk_kernel(
    const float* __restrict__ A, int K, int Kc,
    const float* __restrict__ W, float* __restrict__ partial, int N) {
    __shared__ float sA[64][33];
    __shared__ float sW[32][65];
    int tid = threadIdx.x;
    int g = tid >> 6, nn = tid & 63;
    int n0 = blockIdx.x * 64;
    int k0 = blockIdx.y * Kc;
    float acc[16];
#pragma unroll
    for (int i = 0; i < 16; i++) acc[i] = 0.f;

    for (int kc = k0; kc < k0 + Kc; kc += 32) {
        for (int idx = tid; idx < 2048; idx += 256) {
            int bb = idx >> 5, kk = idx & 31;
            sA[bb][kk] = A[(size_t)bb * K + kc + kk];
        }
        for (int idx = tid; idx < 2048; idx += 256) {
            int kk = idx >> 6, n_ = idx & 63;
            sW[kk][n_] = W[(size_t)(kc + kk) * N + n0 + n_];
        }
        __syncthreads();
#pragma unroll 8
        for (int kk = 0; kk < 32; kk++) {
            float w = sW[kk][nn];
#pragma unroll
            for (int bl = 0; bl < 16; bl++)
                acc[bl] += sA[g * 16 + bl][kk] * w;
        }
        __syncthreads();
    }
    float* out = partial + (size_t)blockIdx.y * 64 * N;
#pragma unroll
    for (int bl = 0; bl < 16; bl++)
        out[(size_t)(g * 16 + bl) * N + n0 + nn] = acc[bl];
}

// act: 0 none, 1 relu, 2 phi
__global__ void reduce_act_kernel(const float* __restrict__ partial, int nsplit,
                                  const float* __restrict__ bias,
                                  float* __restrict__ out, int N, int out_stride, int act) {
    int i = blockIdx.x * blockDim.x + threadIdx.x;
    if (i >= 64 * N) return;
    int b = i / N, n = i - b * N;
    float acc = bias ? bias[n] : 0.f;
    for (int s = 0; s < nsplit; s++) acc += partial[(size_t)s * 64 * N + i];
    if (act == 1) acc = fmaxf(acc, 0.f);
    else if (act == 2) acc = phi_f(acc);
    out[(size_t)b * out_stride + n] = acc;
}

// ---------------- K GEMM + fused wdot: w_part = sum over half-head of phi(kv@wk+bk)*pq --------
#define KV_TM 128
#define KV_TN 256
#define KV_SA_BYTES (128 * 80)                 // row stride 80B = 32 bf16 + 16B pad
#define KV_SB_BYTES (256 * 80)
#define KV_STAGE_BYTES (KV_SA_BYTES + KV_SB_BYTES)   // 30720
#define KV_SMEM_BYTES (4 * KV_STAGE_BYTES)           // 122880

__global__ void __launch_bounds__(512, 1) gemm_kw_kernel(const float* __restrict__ bk) {
    extern __shared__ char sm_raw[];
    uint32 base = smem_u32(sm_raw);
    int tid = threadIdx.x, warp = tid >> 5, lane = tid & 31;
    int gid = lane >> 2, tig = lane & 3;
    int wm = warp >> 3, wn = warp & 7;             // 2 x 8 warp grid, warp tile 64x32
    int n0 = blockIdx.x * KV_TN, m0 = blockIdx.y * KV_TM;

    const __nv_bfloat16* baseA = g_kv  + (size_t)m0 * 1024;
    const __nv_bfloat16* baseB = g_wkT + (size_t)n0 * 1024;

    float acc[4][4][4];
#pragma unroll
    for (int mi = 0; mi < 4; mi++)
#pragma unroll
        for (int ni = 0; ni < 4; ni++)
#pragma unroll
            for (int q = 0; q < 4; q++) acc[mi][ni][q] = 0.f;

    auto load_chunk = [&](int c, int s) {
        uint32 sa = base + s * KV_STAGE_BYTES;
        uint32 sb = sa + KV_SA_BYTES;
        int kc = c * 32;
        {   // A: 512 x 16B
            int row = tid >> 2, seg = tid & 3;
            CP_ASYNC16(sa + row * 80 + seg * 16,
                       baseA + (size_t)row * 1024 + kc + seg * 8);
        }
#pragma unroll
        for (int t = 0; t < 2; t++) {              // B: 1024 x 16B
            int i = tid + t * 512;
            int row = i >> 2, seg = i & 3;
            CP_ASYNC16(sb + row * 80 + seg * 16,
                       baseB + (size_t)row * 1024 + kc + seg * 8);
        }
    };

    load_chunk(0, 0); CP_COMMIT();
    load_chunk(1, 1); CP_COMMIT();
    load_chunk(2, 2); CP_COMMIT();

    int rowA_off = (wm * 64 + (lane & 15)) * 80 + (lane >> 4) * 16;
    int rowB_off = (wn * 32 + (lane & 7) + ((lane >> 4) << 3)) * 80 + ((lane >> 3) & 1) * 16;

    for (int c = 0; c < 32; c++) {
        if (c <= 29)      { CP_WAIT(2); }
        else if (c == 30) { CP_WAIT(1); }
        else              { CP_WAIT(0); }
        __syncthreads();
        if (c + 3 < 32) { load_chunk(c + 3, (c + 3) & 3); CP_COMMIT(); }

        uint32 sa = base + (c & 3) * KV_STAGE_BYTES;
        uint32 sb = sa + KV_SA_BYTES;
#pragma unroll
        for (int ks = 0; ks < 2; ks++) {
            uint32 afr[4][4], bfr[4][2];
#pragma unroll
            for (int mi = 0; mi < 4; mi++)
                LDSM4(afr[mi][0], afr[mi][1], afr[mi][2], afr[mi][3],
                      sa + rowA_off + mi * 16 * 80 + ks * 32);
#pragma unroll
            for (int nj = 0; nj < 2; nj++)
                LDSM4(bfr[2 * nj][0], bfr[2 * nj][1], bfr[2 * nj + 1][0], bfr[2 * nj + 1][1],
                      sb + rowB_off + nj * 16 * 80 + ks * 32);
#pragma unroll
            for (int mi = 0; mi < 4; mi++)
#pragma unroll
                for (int ni = 0; ni < 4; ni++)
                    mma16816(acc[mi][ni], afr[mi], bfr[ni]);
        }
    }

    // fused epilogue: w-partials = sum_{cols of this warp's half-head} phi(y+bk)*pq
    int b = m0 >> 11;
    int s_base = m0 & 2047;
    int hh = (n0 >> 6) + (wn >> 1);
    int half = wn & 1;

    float pqv[8], bkv[8];
#pragma unroll
    for (int ni = 0; ni < 4; ni++) {
        int ng = n0 + wn * 32 + ni * 8 + tig * 2;
        pqv[2 * ni]     = g_pq[b * 1024 + ng];
        pqv[2 * ni + 1] = g_pq[b * 1024 + ng + 1];
        bkv[2 * ni]     = bk[ng];
        bkv[2 * ni + 1] = bk[ng + 1];
    }
    float* wp = g_wpart[half] + (size_t)(b * 16 + hh) * 2048;
#pragma unroll
    for (int mi = 0; mi < 4; mi++) {
        float p0 = 0.f, p1 = 0.f;
#pragma unroll
        for (int ni = 0; ni < 4; ni++) {
            p0 += phi_f(acc[mi][ni][0] + bkv[2 * ni]) * pqv[2 * ni]
                + phi_f(acc[mi][ni][1] + bkv[2 * ni + 1]) * pqv[2 * ni + 1];
            p1 += phi_f(acc[mi][ni][2] + bkv[2 * ni]) * pqv[2 * ni]
                + phi_f(acc[mi][ni][3] + bkv[2 * ni + 1]) * pqv[2 * ni + 1];
        }
        p0 += __shfl_xor_sync(0xFFFFFFFFu, p0, 1);
        p0 += __shfl_xor_sync(0xFFFFFFFFu, p0, 2);
        p1 += __shfl_xor_sync(0xFFFFFFFFu, p1, 1);
        p1 += __shfl_xor_sync(0xFFFFFFFFu, p1, 2);
        if (tig == 0) {
            int s0 = s_base + wm * 64 + mi * 16 + gid;
            wp[s0]     = p0;
            wp[s0 + 8] = p1;
        }
    }
}

// ---------------- wden: w = part0 + part1 (-> bf16) ; den = sum_s w (fp32) ----------------
__global__ void __launch_bounds__(256) wden_kernel() {
    __shared__ float sred[256];
    int bh = blockIdx.x, tid = threadIdx.x;
    size_t base = (size_t)bh * 2048;
    float dsum = 0.f;
#pragma unroll
    for (int i = 0; i < 8; i++) {
        int s = tid + i * 256;
        float wv = g_wpart[0][base + s] + g_wpart[1][base + s];
        g_wbf[base + s] = __float2bfloat16(wv);
        dsum += wv;
    }
    sred[tid] = dsum;
    __syncthreads();
#pragma unroll
    for (int off = 128; off >= 1; off >>= 1) {
        if (tid < off) sred[tid] += sred[tid + off];
        __syncthreads();
    }
    if (tid == 0) g_den[bh] = sred[0];
}

// ---------------- ugemm (mma): u[b][16][1024] = w_bf[b][16][2048] @ kv[b][2048][1024] --------
// grid (8 n-tiles of 128, 64 b), block 128 (4 warps, each N=32)
__global__ void __launch_bounds__(128) ugemm_kernel() {
    __shared__ __nv_bfloat16 sA[16][74];   // [h][s_local], 74-stride: conflict-free
    __shared__ __nv_bfloat16 sB[128][74];  // [e_local][s_local] (transposed kv)
    int tid = threadIdx.x, warp = tid >> 5, lane = tid & 31;
    int gid = lane >> 2, tig = lane & 3;
    int n0 = blockIdx.x * 128, b = blockIdx.y;
    const __nv_bfloat16* A  = g_wbf + (size_t)b * 16 * 2048;
    const __nv_bfloat16* KV = g_kv  + (size_t)b * 2048 * 1024;

    float acc[4][4];
#pragma unroll
    for (int ni = 0; ni < 4; ni++)
#pragma unroll
        for (int q = 0; q < 4; q++) acc[ni][q] = 0.f;

    for (int sc = 0; sc < 2048; sc += 64) {
        // A: 16 x 64 bf16 = 512 uint32
#pragma unroll
        for (int t = 0; t < 4; t++) {
            int idx = tid + t * 128;
            int h = idx >> 5, sl = (idx & 31) * 2;
            *(uint32*)&sA[h][sl] = *(const uint32*)&A[(size_t)h * 2048 + sc + sl];
        }
        // B: kv chunk 64s x 128e, transposed store
#pragma unroll
        for (int t = 0; t < 32; t++) {
            int idx = tid + t * 128;
            int s_l = idx >> 6, ep = idx & 63;
            uint32 v = *(const uint32*)&KV[(size_t)(sc + s_l) * 1024 + n0 + ep * 2];
            __nv_bfloat162 p = *(__nv_bfloat162*)&v;
            sB[ep * 2][s_l]     = p.x;
            sB[ep * 2 + 1][s_l] = p.y;
        }
        __syncthreads();
#pragma unroll
        for (int ks = 0; ks < 4; ks++) {
            int k = ks * 16;
            uint32 afr[4], bfr[4][2];
            afr[0] = *(uint32*)&sA[gid][k + tig * 2];
            afr[1] = *(uint32*)&sA[gid + 8][k + tig * 2];
            afr[2] = *(uint32*)&sA[gid][k + tig * 2 + 8];
            afr[3] = *(uint32*)&sA[gid + 8][k + tig * 2 + 8];
#pragma unroll
            for (int ni = 0; ni < 4; ni++) {
                int n = warp * 32 + ni * 8 + gid;
                bfr[ni][0] = *(uint32*)&sB[n][k + tig * 2];
                bfr[ni][1] = *(uint32*)&sB[n][k + tig * 2 + 8];
            }
#pragma unroll
            for (int ni = 0; ni < 4; ni++) mma16816(acc[ni], afr, bfr[ni]);
        }
        __syncthreads();
    }

    float* ub = g_u + (size_t)b * 16 * 1024;
#pragma unroll
    for (int ni = 0; ni < 4; ni++) {
        int c = n0 + warp * 32 + ni * 8 + tig * 2;
        ub[gid * 1024 + c]           = acc[ni][0];
        ub[gid * 1024 + c + 1]       = acc[ni][1];
        ub[(gid + 8) * 1024 + c]     = acc[ni][2];
        ub[(gid + 8) * 1024 + c + 1] = acc[ni][3];
    }
}

// ---------------- numk: attn = (u.wv_h + den*bv)/(den+eps); copy zL -> pre ----------------
__global__ void __launch_bounds__(256) numk_kernel(const float* __restrict__ wv,
                                                   const float* __restrict__ bv,
                                                   const float* __restrict__ zL) {
    __shared__ float su[1024];
    __shared__ float sred[4][64];
    int bh = blockIdx.x;
    int b = bh >> 4, h = bh & 15;
    int tid = threadIdx.x;
    for (int i = tid; i < 1024; i += 256) su[i] = g_u[(size_t)bh * 1024 + i];
    __syncthreads();
    int grp = tid >> 6, c = tid & 63;
    int col = h * 64 + c;
    const float* wcol = wv + col;
    float part = 0.f;
#pragma unroll 4
    for (int e = grp * 256; e < grp * 256 + 256; e++)
        part += su[e] * wcol[(size_t)e * 1024];
    sred[grp][c] = part;
    __syncthreads();
    if (tid < 64) {
        float den = g_den[bh];
        float num = sred[0][tid] + sred[1][tid] + sred[2][tid] + sred[3][tid]
                  + den * bv[h * 64 + tid];
        float attn = num / (den + 1e-6f);
        g_attn[b * 1024 + h * 64 + tid] = attn;
        g_pre[(size_t)b * 2048 + 1024 + h * 64 + tid] = zL[b * 1024 + h * 64 + tid];
    }
}

// ---------------- trace shift + trace processor -> both outputs ----------------
__global__ void __launch_bounds__(256) trace_kernel(const float* __restrict__ zt,
                                                    const float* __restrict__ w1,
                                                    const float* __restrict__ b1,
                                                    const float* __restrict__ w2,
                                                    const float* __restrict__ b2p,
                                                    float* __restrict__ out) {
    __shared__ float sT[64][33];
    __shared__ float sW1[32][64];
    __shared__ float sB1[64];
    __shared__ float sW2[64];
    __shared__ float sRed[4][64];
    int tid = threadIdx.x;
    int r0 = blockIdx.x * 64;
    float* out_act = out;
    float* out_tr = out + BDIM * DDIM;

    for (int idx = tid; idx < 2048; idx += 256) {
        int rr = idx >> 5, mm = idx & 31;
        float v = (mm < 31) ? zt[(size_t)(r0 + rr) * 32 + mm + 1] : g_state[r0 + rr];
        sT[rr][mm] = v;
        out_tr[(size_t)(r0 + rr) * 32 + mm] = v;
    }
    for (int idx = tid; idx < 2048; idx += 256) {
        int m = idx >> 6, hh = idx & 63;
        sW1[m][hh] = w1[idx];
    }
    if (tid < 64) { sB1[tid] = b1[tid]; sW2[tid] = w2[tid]; }
    __syncthreads();

    int rr = tid & 63, part = tid >> 6;
    float acc = 0.f;
#pragma unroll
    for (int hi = 0; hi < 16; hi++) {
        int hh = part * 16 + hi;
        float hs = sB1[hh];
#pragma unroll
        for (int m = 0; m < 32; m++) hs += sT[rr][m] * sW1[m][hh];
        acc += fmaxf(hs, 0.f) * sW2[hh];
    }
    sRed[part][rr] = acc;
    __syncthreads();
    if (tid < 64)
        out_act[r0 + tid] = sRed[0][tid] + sRed[1][tid] + sRed[2][tid] + sRed[3][tid] + b2p[0];
}

// ---------------- launch ----------------
extern "C" void kernel_launch(void* const* d_in, const int* in_sizes, int n_in,
                              void* d_out, int out_size) {
    (void)in_sizes; (void)n_in; (void)out_size;
    const float* zL  = (const float*)d_in[0];
    const float* zt  = (const float*)d_in[1];
    const float* zH  = (const float*)d_in[2];
    const float* x   = (const float*)d_in[3];
    const float* sy  = (const float*)d_in[4];
    const float* qpw = (const float*)d_in[5];
    const float* qpb = (const float*)d_in[6];
    const float* wq  = (const float*)d_in[7];
    const float* bq  = (const float*)d_in[8];
    const float* wk  = (const float*)d_in[9];
    const float* bk  = (const float*)d_in[10];
    const float* wv  = (const float*)d_in[11];
    const float* bv  = (const float*)d_in[12];
    const float* wo  = (const float*)d_in[13];
    const float* bo  = (const float*)d_in[14];
    const float* sw1 = (const float*)d_in[15];
    const float* sb1 = (const float*)d_in[16];
    const float* sw2 = (const float*)d_in[17];
    const float* sb2 = (const float*)d_in[18];
    const float* tw1 = (const float*)d_in[19];
    const float* tb1 = (const float*)d_in[20];
    const float* tw2 = (const float*)d_in[21];
    const float* tb2 = (const float*)d_in[22];
    float* out = (float*)d_out;

    float *p_q, *p_pq, *p_pre, *p_hidden, *p_state, *p_attn, *p_partial;
    cudaGetSymbolAddress((void**)&p_q,       g_q);
    cudaGetSymbolAddress((void**)&p_pq,      g_pq);
    cudaGetSymbolAddress((void**)&p_pre,     g_pre);
    cudaGetSymbolAddress((void**)&p_hidden,  g_hidden);
    cudaGetSymbolAddress((void**)&p_state,   g_state);
    cudaGetSymbolAddress((void**)&p_attn,    g_attn);
    cudaGetSymbolAddress((void**)&p_partial, g_partial);

    cudaFuncSetAttribute(gemm_kw_kernel,
                         cudaFuncAttributeMaxDynamicSharedMemorySize, KV_SMEM_BYTES);

    // weight prep + activation convert
    pack_wT_kernel<<<dim3(32, 32), 256>>>(wk);
    convert_kv_kernel<<<131072, 256>>>(x, zH);

    // q path (split-K): q = sy@qp_w + qp_b ; pq = phi(q@wq + bq)
    gemm_splitk_kernel<<<dim3(16, 4), 256>>>(sy, SYNCD, 128, qpw, p_partial, 1024);
    reduce_act_kernel<<<256, 256>>>(p_partial, 4, qpb, p_q, 1024, 1024, 0);
    gemm_splitk_kernel<<<dim3(16, 8), 256>>>(p_q, 1024, 128, wq, p_partial, 1024);
    reduce_act_kernel<<<256, 256>>>(p_partial, 8, bq, p_pq, 1024, 1024, 2);

    // K projection GEMM with fused wdot epilogue (pk never materialized)
    gemm_kw_kernel<<<dim3(4, 1024), 512, KV_SMEM_BYTES>>>(bk);

    // w(bf16) + den(fp32)
    wden_kernel<<<1024, 256>>>();

    // u = w @ kv on tensor cores (fp32 accum, full K per CTA)
    ugemm_kernel<<<dim3(8, 64), 128>>>();

    // attn = (u@wv_h + den*bv)/(den+eps); copy zL -> pre[:,1024:]
    numk_kernel<<<1024, 256>>>(wv, bv, zL);

    // attn_out = attn @ wo + bo -> pre[:,0:1024]
    gemm_splitk_kernel<<<dim3(16, 8), 256>>>(p_attn, 1024, 128, wo, p_partial, 1024);
    reduce_act_kernel<<<256, 256>>>(p_partial, 8, bo, p_pre, 1024, 2048, 0);

    // synapse MLP
    gemm_splitk_kernel<<<dim3(32, 8), 256>>>(p_pre, 2048, 256, sw1, p_partial, 2048);
    reduce_act_kernel<<<512, 256>>>(p_partial, 8, sb1, p_hidden, 2048, 2048, 1);
    gemm_splitk_kernel<<<dim3(16, 8), 256>>>(p_hidden, 2048, 256, sw2, p_partial, 1024);
    reduce_act_kernel<<<256, 256>>>(p_partial, 8, sb2, p_state, 1024, 1024, 0);

    // trace update + processor -> writes both outputs
    trace_kernel<<<1024, 256>>>(zt, tw1, tb1, tw2, tb2, out);
}